// round 2
// baseline (speedup 1.0000x reference)
#include <cuda_runtime.h>
#include <math.h>

// Problem constants
constexpr int B = 64, T = 256, C = 512, H = 8, D = 64;
constexpr int M = B * T;        // 16384 rows
constexpr int N3 = 3 * H * D;   // 1536 qkv columns

// Scratch (allocation-free: __device__ globals)
__device__ float g_q[(size_t)B * H * T * D];     // [B,H,T,D]
__device__ float g_k[(size_t)B * H * T * D];
__device__ float g_v[(size_t)B * H * T * D];
__device__ float g_attn[(size_t)M * C];          // [B*T, H*D]

// ---------------------------------------------------------------------------
// Kernel 1: fused QKV projection GEMM.  Y[M, 1536] = X[M,512] @ Wcat
// column j = kind*512 + h*64 + d  (kind: 0=q,1=k,2=v)
// 128x128 block tile, BK=8, 256 threads, 8x8 micro-tile per thread.
// ---------------------------------------------------------------------------
__global__ void __launch_bounds__(256) qkv_gemm_kernel(
    const float* __restrict__ x,
    const float* __restrict__ wq, const float* __restrict__ wk, const float* __restrict__ wv,
    const float* __restrict__ bqp, const float* __restrict__ bkp, const float* __restrict__ bvp)
{
    __shared__ __align__(16) float As[8][128];   // A transposed: As[k][m]
    __shared__ __align__(16) float Bs[8][128];   // Bs[k][n]

    const int n0 = blockIdx.x * 128;
    const int m0 = blockIdx.y * 128;
    const int tid = threadIdx.x;
    const int tx = tid & 15;        // n direction (x8)
    const int ty = tid >> 4;        // m direction (x8)

    const int kind = n0 >> 9;       // tile never straddles a 512 boundary
    const float* w    = (kind == 0) ? wq  : (kind == 1) ? wk  : wv;
    const float* bias = (kind == 0) ? bqp : (kind == 1) ? bkp : bvp;
    float* dstbuf     = (kind == 0) ? g_q : (kind == 1) ? g_k : g_v;

    // A-tile loader mapping: 128 rows x 8 k, one float4 per thread
    const int arow = tid >> 1;
    const int akg  = (tid & 1) * 4;
    // B-tile loader mapping: 8 k rows x 128 n, one float4 per thread
    const int brow = tid >> 5;
    const int bcol = (tid & 31) * 4;
    const int jg   = n0 + bcol;
    const int lh   = (jg >> 6) & 7;
    const int ld   = jg & 63;
    const float* wptr = w + (size_t)lh * C * D + ld;   // + (k)*D walks c

    float acc[8][8];
    #pragma unroll
    for (int i = 0; i < 8; i++)
        #pragma unroll
        for (int j = 0; j < 8; j++) acc[i][j] = 0.f;

    const float* aptr = x + (size_t)(m0 + arow) * C + akg;

    for (int k0 = 0; k0 < C; k0 += 8) {
        float4 av = *(const float4*)(aptr + k0);
        As[akg + 0][arow] = av.x;
        As[akg + 1][arow] = av.y;
        As[akg + 2][arow] = av.z;
        As[akg + 3][arow] = av.w;
        float4 wv4 = *(const float4*)(wptr + (size_t)(k0 + brow) * D);
        *(float4*)&Bs[brow][bcol] = wv4;
        __syncthreads();
        #pragma unroll
        for (int kk = 0; kk < 8; kk++) {
            float a[8], bf[8];
            *(float4*)&a[0]  = *(const float4*)&As[kk][ty * 8];
            *(float4*)&a[4]  = *(const float4*)&As[kk][ty * 8 + 4];
            *(float4*)&bf[0] = *(const float4*)&Bs[kk][tx * 8];
            *(float4*)&bf[4] = *(const float4*)&Bs[kk][tx * 8 + 4];
            #pragma unroll
            for (int i = 0; i < 8; i++)
                #pragma unroll
                for (int j = 0; j < 8; j++)
                    acc[i][j] += a[i] * bf[j];
        }
        __syncthreads();
    }

    // Write to [B,H,T,D] scratch with bias
    const int jc = n0 + tx * 8;
    const int oh = (jc >> 6) & 7;
    const int od = jc & 63;
    float bvals[8];
    #pragma unroll
    for (int j = 0; j < 8; j++) bvals[j] = bias[oh * D + od + j];

    #pragma unroll
    for (int i = 0; i < 8; i++) {
        const int m  = m0 + ty * 8 + i;
        const int ob = m >> 8;
        const int ot = m & 255;
        float* dst = dstbuf + (((size_t)(ob * H + oh)) * T + ot) * D + od;
        float4 v0, v1;
        v0.x = acc[i][0] + bvals[0]; v0.y = acc[i][1] + bvals[1];
        v0.z = acc[i][2] + bvals[2]; v0.w = acc[i][3] + bvals[3];
        v1.x = acc[i][4] + bvals[4]; v1.y = acc[i][5] + bvals[5];
        v1.z = acc[i][6] + bvals[6]; v1.w = acc[i][7] + bvals[7];
        *(float4*)(dst)     = v0;
        *(float4*)(dst + 4) = v1;
    }
}

// ---------------------------------------------------------------------------
// Kernel 2: attention.  One block per (qtile, h, b).  Full K/V in smem.
// ---------------------------------------------------------------------------
constexpr int QS_OFF = 0;                    // Qs[64][65]
constexpr int KS_OFF = QS_OFF + 64 * 65;     // Ks[256][65]
constexpr int VS_OFF = KS_OFF + 256 * 65;    // Vs[256][64]
constexpr int ST_OFF = VS_OFF + 256 * 64;    // St[256][68]  (St[s][i])
constexpr int L_OFF  = ST_OFF + 256 * 68;    // l[64]
constexpr int SMEM_FLOATS = L_OFF + 64;
constexpr size_t SMEM_BYTES = (size_t)SMEM_FLOATS * 4;   // 218,624 B

__global__ void __launch_bounds__(256) attn_kernel()
{
    extern __shared__ float sm[];
    float* Qs = sm + QS_OFF;
    float* Ks = sm + KS_OFF;
    float* Vs = sm + VS_OFF;
    float* St = sm + ST_OFF;
    float* lr = sm + L_OFF;

    const int qt  = blockIdx.x;            // 0..3
    const int hh  = blockIdx.y;
    const int bb  = blockIdx.z;
    const int tid = threadIdx.x;
    const int S_lim = (qt + 1) * 64;       // causal: keys < S_lim
    const int t0 = qt * 64;

    const size_t base = ((size_t)(bb * H + hh)) * T * D;
    const float* qp = g_q + base;
    const float* kp = g_k + base;
    const float* vp = g_v + base;

    // Load Q tile (64x64), transposed access pattern needs no transpose
    for (int idx = tid; idx < 64 * 16; idx += 256) {
        int i = idx >> 4, dg = (idx & 15) * 4;
        float4 v4 = *(const float4*)(qp + (size_t)(t0 + i) * D + dg);
        Qs[i * 65 + dg + 0] = v4.x; Qs[i * 65 + dg + 1] = v4.y;
        Qs[i * 65 + dg + 2] = v4.z; Qs[i * 65 + dg + 3] = v4.w;
    }
    // Load K rows [0, S_lim)
    for (int idx = tid; idx < S_lim * 16; idx += 256) {
        int s = idx >> 4, dg = (idx & 15) * 4;
        float4 v4 = *(const float4*)(kp + (size_t)s * D + dg);
        Ks[s * 65 + dg + 0] = v4.x; Ks[s * 65 + dg + 1] = v4.y;
        Ks[s * 65 + dg + 2] = v4.z; Ks[s * 65 + dg + 3] = v4.w;
    }
    // Load V rows [0, S_lim)
    for (int idx = tid; idx < S_lim * 16; idx += 256) {
        int s = idx >> 4, dg = (idx & 15) * 4;
        *(float4*)&Vs[s * 64 + dg] = *(const float4*)(vp + (size_t)s * D + dg);
    }
    __syncthreads();

    // ---- S = Q @ K^T, stored transposed St[s][i], causal-masked ----
    {
        const int tx = tid & 31;     // s direction, strided (s = tx + 32r)
        const int ty = tid >> 5;     // i direction (x8)
        const int nR = 2 * (qt + 1); // number of 32-wide s strips needed
        float acc[8][8];
        #pragma unroll
        for (int r = 0; r < 8; r++)
            #pragma unroll
            for (int c = 0; c < 8; c++) acc[r][c] = 0.f;

        for (int d0 = 0; d0 < 64; d0++) {
            float a[8];
            #pragma unroll
            for (int c = 0; c < 8; c++) a[c] = Qs[(ty * 8 + c) * 65 + d0];  // broadcast
            float kf[8];
            #pragma unroll
            for (int r = 0; r < 8; r++) {
                if (r >= nR) break;
                kf[r] = Ks[(tx + 32 * r) * 65 + d0];   // conflict-free (stride 65)
            }
            #pragma unroll
            for (int r = 0; r < 8; r++) {
                if (r >= nR) break;
                #pragma unroll
                for (int c = 0; c < 8; c++)
                    acc[r][c] += a[c] * kf[r];
            }
        }
        const float scale = 0.125f;   // 1/sqrt(64)
        #pragma unroll
        for (int r = 0; r < 8; r++) {
            if (r >= nR) break;
            const int s = tx + 32 * r;
            #pragma unroll
            for (int c = 0; c < 8; c++) {
                const int tg = t0 + ty * 8 + c;
                St[s * 68 + ty * 8 + c] = (s <= tg) ? acc[r][c] * scale : -1e30f;
            }
        }
    }
    __syncthreads();

    // ---- softmax along s for each column i (4 threads per column) ----
    {
        const int i = tid >> 2;
        const int p = tid & 3;
        const int tg = t0 + i;
        float mx = -1e30f;
        for (int s = p; s <= tg; s += 4) mx = fmaxf(mx, St[s * 68 + i]);
        mx = fmaxf(mx, __shfl_xor_sync(0xffffffffu, mx, 1));
        mx = fmaxf(mx, __shfl_xor_sync(0xffffffffu, mx, 2));
        float sum = 0.f;
        for (int s = p; s < S_lim; s += 4) {
            float v = St[s * 68 + i];
            float e = (s <= tg) ? __expf(v - mx) : 0.f;
            St[s * 68 + i] = e;
            sum += e;
        }
        sum += __shfl_xor_sync(0xffffffffu, sum, 1);
        sum += __shfl_xor_sync(0xffffffffu, sum, 2);
        if (p == 0) lr[i] = sum;
    }
    __syncthreads();

    // ---- O = P @ V (64x64), 4x4 micro-tile per thread ----
    {
        const int tx = tid & 15;     // j direction (x4)
        const int ty = tid >> 4;     // i direction (x4)
        float o[4][4];
        #pragma unroll
        for (int ii = 0; ii < 4; ii++)
            #pragma unroll
            for (int jj = 0; jj < 4; jj++) o[ii][jj] = 0.f;

        for (int s = 0; s < S_lim; s++) {
            float4 a4 = *(const float4*)&St[s * 68 + ty * 4];
            float4 b4 = *(const float4*)&Vs[s * 64 + tx * 4];
            float a[4]  = {a4.x, a4.y, a4.z, a4.w};
            float bf[4] = {b4.x, b4.y, b4.z, b4.w};
            #pragma unroll
            for (int ii = 0; ii < 4; ii++)
                #pragma unroll
                for (int jj = 0; jj < 4; jj++)
                    o[ii][jj] += a[ii] * bf[jj];
        }
        #pragma unroll
        for (int ii = 0; ii < 4; ii++) {
            const int i = ty * 4 + ii;
            const float inv = 1.f / lr[i];
            float4 r;
            r.x = o[ii][0] * inv; r.y = o[ii][1] * inv;
            r.z = o[ii][2] * inv; r.w = o[ii][3] * inv;
            *(float4*)(g_attn + ((size_t)bb * T + t0 + i) * C + hh * D + tx * 4) = r;
        }
    }
}

// ---------------------------------------------------------------------------
// Kernel 3: output projection.  out[M,512] = attn[M,512] @ wo[512,512] + bo
// ---------------------------------------------------------------------------
__global__ void __launch_bounds__(256) out_gemm_kernel(
    const float* __restrict__ wo, const float* __restrict__ bo, float* __restrict__ out)
{
    __shared__ __align__(16) float As[8][128];
    __shared__ __align__(16) float Bs[8][128];

    const int n0 = blockIdx.x * 128;
    const int m0 = blockIdx.y * 128;
    const int tid = threadIdx.x;
    const int tx = tid & 15;
    const int ty = tid >> 4;

    const int arow = tid >> 1;
    const int akg  = (tid & 1) * 4;
    const int brow = tid >> 5;
    const int bcol = (tid & 31) * 4;

    float acc[8][8];
    #pragma unroll
    for (int i = 0; i < 8; i++)
        #pragma unroll
        for (int j = 0; j < 8; j++) acc[i][j] = 0.f;

    const float* aptr = g_attn + (size_t)(m0 + arow) * C + akg;

    for (int k0 = 0; k0 < C; k0 += 8) {
        float4 av = *(const float4*)(aptr + k0);
        As[akg + 0][arow] = av.x;
        As[akg + 1][arow] = av.y;
        As[akg + 2][arow] = av.z;
        As[akg + 3][arow] = av.w;
        float4 wv4 = *(const float4*)(wo + (size_t)(k0 + brow) * C + n0 + bcol);
        *(float4*)&Bs[brow][bcol] = wv4;
        __syncthreads();
        #pragma unroll
        for (int kk = 0; kk < 8; kk++) {
            float a[8], bf[8];
            *(float4*)&a[0]  = *(const float4*)&As[kk][ty * 8];
            *(float4*)&a[4]  = *(const float4*)&As[kk][ty * 8 + 4];
            *(float4*)&bf[0] = *(const float4*)&Bs[kk][tx * 8];
            *(float4*)&bf[4] = *(const float4*)&Bs[kk][tx * 8 + 4];
            #pragma unroll
            for (int i = 0; i < 8; i++)
                #pragma unroll
                for (int j = 0; j < 8; j++)
                    acc[i][j] += a[i] * bf[j];
        }
        __syncthreads();
    }

    float bvals[8];
    #pragma unroll
    for (int j = 0; j < 8; j++) bvals[j] = bo[n0 + tx * 8 + j];

    #pragma unroll
    for (int i = 0; i < 8; i++) {
        const int m = m0 + ty * 8 + i;
        float* dst = out + (size_t)m * C + n0 + tx * 8;
        float4 v0, v1;
        v0.x = acc[i][0] + bvals[0]; v0.y = acc[i][1] + bvals[1];
        v0.z = acc[i][2] + bvals[2]; v0.w = acc[i][3] + bvals[3];
        v1.x = acc[i][4] + bvals[4]; v1.y = acc[i][5] + bvals[5];
        v1.z = acc[i][6] + bvals[6]; v1.w = acc[i][7] + bvals[7];
        *(float4*)(dst)     = v0;
        *(float4*)(dst + 4) = v1;
    }
}

// ---------------------------------------------------------------------------
extern "C" void kernel_launch(void* const* d_in, const int* in_sizes, int n_in,
                              void* d_out, int out_size)
{
    const float* x  = (const float*)d_in[0];
    const float* wq = (const float*)d_in[1];
    const float* wk = (const float*)d_in[2];
    const float* wv = (const float*)d_in[3];
    const float* bq = (const float*)d_in[4];
    const float* bk = (const float*)d_in[5];
    const float* bv = (const float*)d_in[6];
    const float* wo = (const float*)d_in[7];
    const float* bo = (const float*)d_in[8];
    float* out = (float*)d_out;

    cudaFuncSetAttribute(attn_kernel, cudaFuncAttributeMaxDynamicSharedMemorySize,
                         (int)SMEM_BYTES);

    qkv_gemm_kernel<<<dim3(N3 / 128, M / 128), 256>>>(x, wq, wk, wv, bq, bk, bv);
    attn_kernel<<<dim3(T / 64, H, B), 256, SMEM_BYTES>>>();
    out_gemm_kernel<<<dim3(C / 128, M / 128), 256>>>(wo, bo, out);
}

// round 8
// speedup vs baseline: 1.4943x; 1.4943x over previous
#include <cuda_runtime.h>
#include <cuda.h>
#include <math.h>
#include <cstdint>

// Problem constants
constexpr int B = 64, T = 256, C = 512, H = 8, D = 64;
constexpr int M = B * T;        // 16384 rows
constexpr int N3 = 3 * H * D;   // 1536 qkv columns

// Scratch (allocation-free: __device__ globals)
__device__ float g_q[(size_t)B * H * T * D];     // [B,H,T,D]
__device__ float g_k[(size_t)B * H * T * D];
__device__ float g_v[(size_t)B * H * T * D];
__device__ float g_attn[(size_t)M * C];          // [B*T, H*D]
__device__ float g_wt[(size_t)N3 * C];           // K-major qkv weights [1536][512]
__device__ float g_wot[(size_t)C * C];           // K-major wo [512][512]
__device__ float g_bcat[N3];                     // concatenated qkv bias

// ---------------------------------------------------------------------------
// Helpers
// ---------------------------------------------------------------------------
__device__ __forceinline__ uint32_t f2tf32(float v) {
    uint32_t u;
    asm("cvt.rna.tf32.f32 %0, %1;" : "=r"(u) : "f"(v));
    return u;
}
__device__ __forceinline__ void mma_tf32(float* c, const uint32_t* a, const uint32_t* b) {
    asm volatile(
        "mma.sync.aligned.m16n8k8.row.col.f32.tf32.tf32.f32 "
        "{%0,%1,%2,%3}, {%4,%5,%6,%7}, {%8,%9}, {%0,%1,%2,%3};"
        : "+f"(c[0]), "+f"(c[1]), "+f"(c[2]), "+f"(c[3])
        : "r"(a[0]), "r"(a[1]), "r"(a[2]), "r"(a[3]), "r"(b[0]), "r"(b[1]));
}

// ---------------------------------------------------------------------------
// Weight transpose kernels (run once per launch; ~4 MB total)
// ---------------------------------------------------------------------------
__global__ void transpose_qkv_kernel(const float* __restrict__ wq,
                                     const float* __restrict__ wk,
                                     const float* __restrict__ wv)
{
    __shared__ float t[32][33];
    const int mat = blockIdx.z;          // 0..23 = kind*8 + h
    const int kind = mat >> 3, h = mat & 7;
    const float* src = ((kind == 0) ? wq : (kind == 1) ? wk : wv) + (size_t)h * C * D;
    const int c0 = blockIdx.x * 32, d0 = blockIdx.y * 32;
    const int tx = threadIdx.x, ty = threadIdx.y;
    #pragma unroll
    for (int i = 0; i < 32; i += 8)
        t[ty + i][tx] = src[(size_t)(c0 + ty + i) * D + d0 + tx];
    __syncthreads();
    float* dst = g_wt + (size_t)(kind * 512 + h * 64) * C;
    #pragma unroll
    for (int i = 0; i < 32; i += 8)
        dst[(size_t)(d0 + ty + i) * C + c0 + tx] = t[tx][ty + i];
}

__global__ void transpose_wo_kernel(const float* __restrict__ wo)
{
    __shared__ float t[32][33];
    const int n0 = blockIdx.x * 32, k0 = blockIdx.y * 32;
    const int tx = threadIdx.x, ty = threadIdx.y;
    #pragma unroll
    for (int i = 0; i < 32; i += 8)
        t[ty + i][tx] = wo[(size_t)(k0 + ty + i) * C + n0 + tx];
    __syncthreads();
    #pragma unroll
    for (int i = 0; i < 32; i += 8)
        g_wot[(size_t)(n0 + ty + i) * C + k0 + tx] = t[tx][ty + i];
}

__global__ void bias_concat_kernel(const float* __restrict__ bq,
                                   const float* __restrict__ bk,
                                   const float* __restrict__ bv)
{
    int idx = blockIdx.x * 256 + threadIdx.x;
    if (idx < N3) {
        int kind = idx >> 9, i = idx & 511;
        g_bcat[idx] = (kind == 0) ? bq[i] : (kind == 1) ? bk[i] : bv[i];
    }
}

// ---------------------------------------------------------------------------
// mma.sync tf32 GEMM:  Dmat[m, n] = sum_k A[m,k] * Bt[n,k]  (+bias, scatter)
// CTA tile 128x128, BK=32, 8 warps (2 x 4), warp tile 64x32,
// mma.m16n8k8 fragment grid 4x4, double-buffered padded smem.
// mode 0: A = x param, Bt = g_wt, bias = g_bcat, scatter to g_q/g_k/g_v
// mode 1: A = g_attn,  Bt = g_wot, bias = bo,     write d_out [m][512]
// ---------------------------------------------------------------------------
constexpr int PAD = 4;
constexpr int LDS_ROW = 32 + PAD;                 // 36 floats
constexpr int TILE_FLOATS = 128 * LDS_ROW;        // per A or B tile, 18432 B
constexpr int BUF_FLOATS = 2 * TILE_FLOATS;       // A + B
constexpr int SMEM_GEMM_FLOATS = 2 * BUF_FLOATS;  // double buffer
constexpr int SMEM_GEMM = SMEM_GEMM_FLOATS * 4;   // 147,456... no: 2*2*18432*... 

// recompute: 2 buffers * (A 18432B + B 18432B) = 73,728 B
constexpr int SMEM_GEMM_BYTES = 2 * 2 * TILE_FLOATS * 4;

__global__ void __launch_bounds__(256, 1) gemm_mma_kernel(
    const float* __restrict__ xin, const float* __restrict__ bo_in,
    float* __restrict__ outp, int mode)
{
    extern __shared__ float sm[];
    const int tid = threadIdx.x;
    const int wid = tid >> 5;
    const int lid = tid & 31;
    const int gid = lid >> 2;           // lane / 4
    const int tig = lid & 3;            // lane % 4

    const int wm = wid & 1;             // warp row (64 rows each)
    const int wn = wid >> 1;            // warp col (32 cols each)

    const float* A    = (mode == 0) ? xin : g_attn;
    const float* Bt   = (mode == 0) ? g_wt : g_wot;
    const float* bias = (mode == 0) ? g_bcat : bo_in;

    const int n0 = blockIdx.x * 128;
    const int m0 = blockIdx.y * 128;

    float acc[4][4][4];
    #pragma unroll
    for (int i = 0; i < 4; i++)
        #pragma unroll
        for (int j = 0; j < 4; j++)
            #pragma unroll
            for (int q = 0; q < 4; q++) acc[i][j][q] = 0.f;

    // global loader mapping: idx = tid + p*256; row = idx>>3, kq = (idx&7)*4
    const int lrow = tid >> 3;            // row base (stride 32 over p)
    const int lkq  = (tid & 7) * 4;
    const float* aSrc = A  + (size_t)(m0 + lrow) * C + lkq;
    const float* bSrc = Bt + (size_t)(n0 + lrow) * C + lkq;

    float* As[2] = { sm,               sm + BUF_FLOATS };
    float* Bs[2] = { sm + TILE_FLOATS, sm + BUF_FLOATS + TILE_FLOATS };

    // preload tile 0
    {
        #pragma unroll
        for (int p = 0; p < 4; p++) {
            float4 av = *(const float4*)(aSrc + (size_t)(p * 32) * C);
            float4 bv = *(const float4*)(bSrc + (size_t)(p * 32) * C);
            uint32_t* ad = (uint32_t*)&As[0][(p * 32 + lrow) * LDS_ROW + lkq];
            uint32_t* bd = (uint32_t*)&Bs[0][(p * 32 + lrow) * LDS_ROW + lkq];
            ad[0] = f2tf32(av.x); ad[1] = f2tf32(av.y); ad[2] = f2tf32(av.z); ad[3] = f2tf32(av.w);
            bd[0] = f2tf32(bv.x); bd[1] = f2tf32(bv.y); bd[2] = f2tf32(bv.z); bd[3] = f2tf32(bv.w);
        }
    }
    __syncthreads();

    int buf = 0;
    for (int s = 0; s < 16; s++) {
        // prefetch next tile into registers
        float4 pa[4], pb[4];
        if (s + 1 < 16) {
            const int k0 = (s + 1) * 32;
            #pragma unroll
            for (int p = 0; p < 4; p++) {
                pa[p] = *(const float4*)(aSrc + (size_t)(p * 32) * C + k0);
                pb[p] = *(const float4*)(bSrc + (size_t)(p * 32) * C + k0);
            }
        }

        // compute on current buffer
        const float* Ab = As[buf];
        const float* Bb = Bs[buf];
        #pragma unroll
        for (int ks = 0; ks < 4; ks++) {
            const int k = ks * 8;
            uint32_t af[4][4];
            #pragma unroll
            for (int mf = 0; mf < 4; mf++) {
                const int r0 = (wm * 64 + mf * 16 + gid) * LDS_ROW + k + tig;
                af[mf][0] = ((const uint32_t*)Ab)[r0];
                af[mf][1] = ((const uint32_t*)Ab)[r0 + 8 * LDS_ROW];
                af[mf][2] = ((const uint32_t*)Ab)[r0 + 4];
                af[mf][3] = ((const uint32_t*)Ab)[r0 + 8 * LDS_ROW + 4];
            }
            uint32_t bf[4][2];
            #pragma unroll
            for (int nf = 0; nf < 4; nf++) {
                const int c0 = (wn * 32 + nf * 8 + gid) * LDS_ROW + k + tig;
                bf[nf][0] = ((const uint32_t*)Bb)[c0];
                bf[nf][1] = ((const uint32_t*)Bb)[c0 + 4];
            }
            #pragma unroll
            for (int mf = 0; mf < 4; mf++)
                #pragma unroll
                for (int nf = 0; nf < 4; nf++)
                    mma_tf32(acc[mf][nf], af[mf], bf[nf]);
        }
        __syncthreads();        // all warps done reading buf / prev writes to buf^1
        if (s + 1 < 16) {
            float* ad0 = As[buf ^ 1];
            float* bd0 = Bs[buf ^ 1];
            #pragma unroll
            for (int p = 0; p < 4; p++) {
                uint32_t* ad = (uint32_t*)&ad0[(p * 32 + lrow) * LDS_ROW + lkq];
                uint32_t* bd = (uint32_t*)&bd0[(p * 32 + lrow) * LDS_ROW + lkq];
                ad[0] = f2tf32(pa[p].x); ad[1] = f2tf32(pa[p].y);
                ad[2] = f2tf32(pa[p].z); ad[3] = f2tf32(pa[p].w);
                bd[0] = f2tf32(pb[p].x); bd[1] = f2tf32(pb[p].y);
                bd[2] = f2tf32(pb[p].z); bd[3] = f2tf32(pb[p].w);
            }
            __syncthreads();
        }
        buf ^= 1;
    }

    // Epilogue: acc[mf][nf] fragment (16x8):
    //   c0,c1 -> (row = gid,     col = 2*tig + {0,1})
    //   c2,c3 -> (row = gid + 8, col = 2*tig + {0,1})
    #pragma unroll
    for (int nf = 0; nf < 4; nf++) {
        const int j = n0 + wn * 32 + nf * 8 + 2 * tig;
        const float b0 = bias[j], b1 = bias[j + 1];

        #pragma unroll
        for (int mf = 0; mf < 4; mf++) {
            const int mrow0 = m0 + wm * 64 + mf * 16 + gid;
            #pragma unroll
            for (int half = 0; half < 2; half++) {
                const int m = mrow0 + half * 8;
                float2 v;
                v.x = acc[mf][nf][half * 2 + 0] + b0;
                v.y = acc[mf][nf][half * 2 + 1] + b1;
                float* dst;
                if (mode == 0) {
                    const int kind = j >> 9;
                    const int hh = (j >> 6) & 7;
                    const int dd = j & 63;
                    const int bb = m >> 8;
                    const int tt = m & 255;
                    float* bufp = (kind == 0) ? g_q : (kind == 1) ? g_k : g_v;
                    dst = bufp + (((size_t)(bb * H + hh)) * T + tt) * D + dd;
                } else {
                    dst = outp + (size_t)m * C + j;
                }
                *(float2*)dst = v;
            }
        }
    }
}

// ---------------------------------------------------------------------------
// Attention kernel (unchanged): one block per (qtile, h, b)
// ---------------------------------------------------------------------------
constexpr int QS_OFF = 0;                    // Qs[64][65]
constexpr int KS_OFF = QS_OFF + 64 * 65;     // Ks[256][65]
constexpr int VS_OFF = KS_OFF + 256 * 65;    // Vs[256][64]
constexpr int ST_OFF = VS_OFF + 256 * 64;    // St[256][68]
constexpr int L_OFF  = ST_OFF + 256 * 68;    // l[64]
constexpr int SMEM_FLOATS = L_OFF + 64;
constexpr size_t SMEM_BYTES = (size_t)SMEM_FLOATS * 4;   // 218,624 B

__global__ void __launch_bounds__(256) attn_kernel()
{
    extern __shared__ float smf[];
    float* Qs = smf + QS_OFF;
    float* Ks = smf + KS_OFF;
    float* Vs = smf + VS_OFF;
    float* St = smf + ST_OFF;
    float* lr_ = smf + L_OFF;

    const int qt  = blockIdx.x;
    const int hh  = blockIdx.y;
    const int bb  = blockIdx.z;
    const int tid = threadIdx.x;
    const int S_lim = (qt + 1) * 64;
    const int t0 = qt * 64;

    const size_t base = ((size_t)(bb * H + hh)) * T * D;
    const float* qp = g_q + base;
    const float* kp = g_k + base;
    const float* vp = g_v + base;

    for (int idx = tid; idx < 64 * 16; idx += 256) {
        int i = idx >> 4, dg = (idx & 15) * 4;
        float4 v4 = *(const float4*)(qp + (size_t)(t0 + i) * D + dg);
        Qs[i * 65 + dg + 0] = v4.x; Qs[i * 65 + dg + 1] = v4.y;
        Qs[i * 65 + dg + 2] = v4.z; Qs[i * 65 + dg + 3] = v4.w;
    }
    for (int idx = tid; idx < S_lim * 16; idx += 256) {
        int s = idx >> 4, dg = (idx & 15) * 4;
        float4 v4 = *(const float4*)(kp + (size_t)s * D + dg);
        Ks[s * 65 + dg + 0] = v4.x; Ks[s * 65 + dg + 1] = v4.y;
        Ks[s * 65 + dg + 2] = v4.z; Ks[s * 65 + dg + 3] = v4.w;
    }
    for (int idx = tid; idx < S_lim * 16; idx += 256) {
        int s = idx >> 4, dg = (idx & 15) * 4;
        *(float4*)&Vs[s * 64 + dg] = *(const float4*)(vp + (size_t)s * D + dg);
    }
    __syncthreads();

    {
        const int tx = tid & 31;
        const int ty = tid >> 5;
        const int nR = 2 * (qt + 1);
        float acc[8][8];
        #pragma unroll
        for (int r = 0; r < 8; r++)
            #pragma unroll
            for (int c = 0; c < 8; c++) acc[r][c] = 0.f;

        for (int d0 = 0; d0 < 64; d0++) {
            float a[8];
            #pragma unroll
            for (int c = 0; c < 8; c++) a[c] = Qs[(ty * 8 + c) * 65 + d0];
            float kf[8];
            #pragma unroll
            for (int r = 0; r < 8; r++) {
                if (r >= nR) break;
                kf[r] = Ks[(tx + 32 * r) * 65 + d0];
            }
            #pragma unroll
            for (int r = 0; r < 8; r++) {
                if (r >= nR) break;
                #pragma unroll
                for (int c = 0; c < 8; c++)
                    acc[r][c] += a[c] * kf[r];
            }
        }
        const float scale = 0.125f;
        #pragma unroll
        for (int r = 0; r < 8; r++) {
            if (r >= nR) break;
            const int s = tx + 32 * r;
            #pragma unroll
            for (int c = 0; c < 8; c++) {
                const int tg = t0 + ty * 8 + c;
                St[s * 68 + ty * 8 + c] = (s <= tg) ? acc[r][c] * scale : -1e30f;
            }
        }
    }
    __syncthreads();

    {
        const int i = tid >> 2;
        const int p = tid & 3;
        const int tg = t0 + i;
        float mx = -1e30f;
        for (int s = p; s <= tg; s += 4) mx = fmaxf(mx, St[s * 68 + i]);
        mx = fmaxf(mx, __shfl_xor_sync(0xffffffffu, mx, 1));
        mx = fmaxf(mx, __shfl_xor_sync(0xffffffffu, mx, 2));
        float sum = 0.f;
        for (int s = p; s < S_lim; s += 4) {
            float v = St[s * 68 + i];
            float e = (s <= tg) ? __expf(v - mx) : 0.f;
            St[s * 68 + i] = e;
            sum += e;
        }
        sum += __shfl_xor_sync(0xffffffffu, sum, 1);
        sum += __shfl_xor_sync(0xffffffffu, sum, 2);
        if (p == 0) lr_[i] = sum;
    }
    __syncthreads();

    {
        const int tx = tid & 15;
        const int ty = tid >> 4;
        float o[4][4];
        #pragma unroll
        for (int ii = 0; ii < 4; ii++)
            #pragma unroll
            for (int jj = 0; jj < 4; jj++) o[ii][jj] = 0.f;

        for (int s = 0; s < S_lim; s++) {
            float4 a4 = *(const float4*)&St[s * 68 + ty * 4];
            float4 b4 = *(const float4*)&Vs[s * 64 + tx * 4];
            float a[4]  = {a4.x, a4.y, a4.z, a4.w};
            float bf[4] = {b4.x, b4.y, b4.z, b4.w};
            #pragma unroll
            for (int ii = 0; ii < 4; ii++)
                #pragma unroll
                for (int jj = 0; jj < 4; jj++)
                    o[ii][jj] += a[ii] * bf[jj];
        }
        #pragma unroll
        for (int ii = 0; ii < 4; ii++) {
            const int i = ty * 4 + ii;
            const float inv = 1.f / lr_[i];
            float4 r;
            r.x = o[ii][0] * inv; r.y = o[ii][1] * inv;
            r.z = o[ii][2] * inv; r.w = o[ii][3] * inv;
            *(float4*)(g_attn + ((size_t)bb * T + t0 + i) * C + hh * D + tx * 4) = r;
        }
    }
}

// ---------------------------------------------------------------------------
extern "C" void kernel_launch(void* const* d_in, const int* in_sizes, int n_in,
                              void* d_out, int out_size)
{
    const float* x  = (const float*)d_in[0];
    const float* wq = (const float*)d_in[1];
    const float* wk = (const float*)d_in[2];
    const float* wv = (const float*)d_in[3];
    const float* bq = (const float*)d_in[4];
    const float* bk = (const float*)d_in[5];
    const float* bv = (const float*)d_in[6];
    const float* wo = (const float*)d_in[7];
    const float* bo = (const float*)d_in[8];
    float* out = (float*)d_out;

    cudaFuncSetAttribute(attn_kernel, cudaFuncAttributeMaxDynamicSharedMemorySize,
                         (int)SMEM_BYTES);
    cudaFuncSetAttribute(gemm_mma_kernel, cudaFuncAttributeMaxDynamicSharedMemorySize,
                         SMEM_GEMM_BYTES);

    transpose_qkv_kernel<<<dim3(16, 2, 24), dim3(32, 8)>>>(wq, wk, wv);
    transpose_wo_kernel<<<dim3(16, 16), dim3(32, 8)>>>(wo);
    bias_concat_kernel<<<6, 256>>>(bq, bk, bv);

    gemm_mma_kernel<<<dim3(N3 / 128, M / 128), 256, SMEM_GEMM_BYTES>>>(x, nullptr, nullptr, 0);
    attn_kernel<<<dim3(T / 64, H, B), 256, SMEM_BYTES>>>();
    gemm_mma_kernel<<<dim3(C / 128, M / 128), 256, SMEM_GEMM_BYTES>>>(nullptr, bo, out, 1);
}

// round 9
// speedup vs baseline: 2.8976x; 1.9391x over previous
#include <cuda_runtime.h>
#include <cuda.h>
#include <math.h>
#include <cstdint>

// Problem constants
constexpr int B = 64, T = 256, C = 512, H = 8, D = 64;
constexpr int M = B * T;        // 16384 rows
constexpr int N3 = 3 * H * D;   // 1536 qkv columns

// Scratch (allocation-free: __device__ globals)
__device__ float g_q[(size_t)B * H * T * D];     // [B,H,T,D]   (tf32-rounded)
__device__ float g_k[(size_t)B * H * T * D];     // [B,H,T,D]   (tf32-rounded)
__device__ float g_v[(size_t)B * H * D * T];     // [B,H,D,T] TRANSPOSED (tf32-rounded)
__device__ float g_attn[(size_t)M * C];          // [B*T, H*D]  (tf32-rounded)
__device__ float g_wt[(size_t)N3 * C];           // K-major qkv weights (tf32-rounded)
__device__ float g_wot[(size_t)C * C];           // K-major wo (tf32-rounded)
__device__ float g_bcat[N3];                     // concatenated qkv bias (fp32)
__device__ float g_xr[(size_t)M * C];            // tf32-rounded x

// ---------------------------------------------------------------------------
// Helpers
// ---------------------------------------------------------------------------
__device__ __forceinline__ uint32_t f2tf32(float v) {
    uint32_t u;
    asm("cvt.rna.tf32.f32 %0, %1;" : "=r"(u) : "f"(v));
    return u;
}
__device__ __forceinline__ float rndtf(float v) { return __uint_as_float(f2tf32(v)); }

__device__ __forceinline__ uint32_t smem_u32(const void* p) {
    uint32_t a;
    asm("{ .reg .u64 t; cvta.to.shared.u64 t, %1; cvt.u32.u64 %0, t; }" : "=r"(a) : "l"(p));
    return a;
}
__device__ __forceinline__ void mma_tf32(float* c, const uint32_t* a, const uint32_t* b) {
    asm volatile(
        "mma.sync.aligned.m16n8k8.row.col.f32.tf32.tf32.f32 "
        "{%0,%1,%2,%3}, {%4,%5,%6,%7}, {%8,%9}, {%0,%1,%2,%3};"
        : "+f"(c[0]), "+f"(c[1]), "+f"(c[2]), "+f"(c[3])
        : "r"(a[0]), "r"(a[1]), "r"(a[2]), "r"(a[3]), "r"(b[0]), "r"(b[1]));
}
#define LDM4(r0, r1, r2, r3, addr)                                              \
    asm volatile("ldmatrix.sync.aligned.m8n8.x4.shared.b16 {%0,%1,%2,%3}, [%4];" \
                 : "=r"(r0), "=r"(r1), "=r"(r2), "=r"(r3) : "r"(addr))

__device__ __forceinline__ void cp16(uint32_t dst, const void* src) {
    asm volatile("cp.async.cg.shared.global [%0], [%1], 16;" :: "r"(dst), "l"(src));
}
#define CP_COMMIT() asm volatile("cp.async.commit_group;" ::: "memory")
#define CP_WAIT1()  asm volatile("cp.async.wait_group 1;" ::: "memory")

// ---------------------------------------------------------------------------
// Prep kernels
// ---------------------------------------------------------------------------
__global__ void cvt_x_kernel(const float4* __restrict__ x)
{
    int i = blockIdx.x * 256 + threadIdx.x;
    float4 v = x[i];
    v.x = rndtf(v.x); v.y = rndtf(v.y); v.z = rndtf(v.z); v.w = rndtf(v.w);
    ((float4*)g_xr)[i] = v;
}

__global__ void transpose_qkv_kernel(const float* __restrict__ wq,
                                     const float* __restrict__ wk,
                                     const float* __restrict__ wv)
{
    __shared__ float t[32][33];
    const int mat = blockIdx.z;          // 0..23 = kind*8 + h
    const int kind = mat >> 3, h = mat & 7;
    const float* src = ((kind == 0) ? wq : (kind == 1) ? wk : wv) + (size_t)h * C * D;
    const int c0 = blockIdx.x * 32, d0 = blockIdx.y * 32;
    const int tx = threadIdx.x, ty = threadIdx.y;
    #pragma unroll
    for (int i = 0; i < 32; i += 8)
        t[ty + i][tx] = src[(size_t)(c0 + ty + i) * D + d0 + tx];
    __syncthreads();
    float* dst = g_wt + (size_t)(kind * 512 + h * 64) * C;
    #pragma unroll
    for (int i = 0; i < 32; i += 8)
        dst[(size_t)(d0 + ty + i) * C + c0 + tx] = rndtf(t[tx][ty + i]);
}

__global__ void transpose_wo_kernel(const float* __restrict__ wo)
{
    __shared__ float t[32][33];
    const int n0 = blockIdx.x * 32, k0 = blockIdx.y * 32;
    const int tx = threadIdx.x, ty = threadIdx.y;
    #pragma unroll
    for (int i = 0; i < 32; i += 8)
        t[ty + i][tx] = wo[(size_t)(k0 + ty + i) * C + n0 + tx];
    __syncthreads();
    #pragma unroll
    for (int i = 0; i < 32; i += 8)
        g_wot[(size_t)(n0 + ty + i) * C + k0 + tx] = rndtf(t[tx][ty + i]);
}

__global__ void bias_concat_kernel(const float* __restrict__ bq,
                                   const float* __restrict__ bk,
                                   const float* __restrict__ bv)
{
    int idx = blockIdx.x * 256 + threadIdx.x;
    if (idx < N3) {
        int kind = idx >> 9, i = idx & 511;
        g_bcat[idx] = (kind == 0) ? bq[i] : (kind == 1) ? bk[i] : bv[i];
    }
}

// ---------------------------------------------------------------------------
// mma.sync tf32 GEMM, cp.async 3-stage + ldmatrix.
// CTA 128x128, BK=32, 8 warps (wm 2 x wn 4), warp tile 64x32, frag 4x4.
// mode 0: A=g_xr, B=g_wt, bias=g_bcat -> scatter q/k/v (v transposed), rounded
// mode 1: A=g_attn, B=g_wot, bias=bo  -> d_out fp32
// ---------------------------------------------------------------------------
constexpr int LDSR = 36;                          // floats per 32-float row (+4 pad)
constexpr int TILEF = 128 * LDSR;                 // 4608 floats per tile
constexpr int STAGEF = 2 * TILEF;                 // A + B
constexpr int GSTAGES = 3;
constexpr int SMEM_GEMM_BYTES = GSTAGES * STAGEF * 4;   // 110,592 B

__global__ void __launch_bounds__(256, 2) gemm_mma_kernel(
    const float* __restrict__ bo_in, float* __restrict__ outp, int mode)
{
    extern __shared__ float sm[];
    const uint32_t smb = smem_u32(sm);
    const int tid = threadIdx.x;
    const int wid = tid >> 5;
    const int lid = tid & 31;
    const int gid = lid >> 2, tig = lid & 3;       // mma epilogue mapping
    const int lg = lid >> 3, lr8 = lid & 7;        // ldmatrix mapping
    const int wm = wid & 1;
    const int wn = wid >> 1;

    const float* A    = (mode == 0) ? g_xr : g_attn;
    const float* Bt   = (mode == 0) ? g_wt : g_wot;
    const float* bias = (mode == 0) ? g_bcat : bo_in;

    const int n0 = blockIdx.x * 128;
    const int m0 = blockIdx.y * 128;

    float acc[4][4][4];
    #pragma unroll
    for (int i = 0; i < 4; i++)
        #pragma unroll
        for (int j = 0; j < 4; j++)
            #pragma unroll
            for (int q = 0; q < 4; q++) acc[i][j][q] = 0.f;

    // cp.async loader mapping
    const int lrow = tid >> 3;
    const int lcol = (tid & 7) * 4;                // float offset in row
    const float* aSrc = A  + (size_t)(m0 + lrow) * C + lcol;
    const float* bSrc = Bt + (size_t)(n0 + lrow) * C + lcol;

    auto issue = [&](int s) {
        const int k0 = s * 32;
        const uint32_t ab = smb + (uint32_t)((s % GSTAGES) * STAGEF) * 4;
        const uint32_t bb = ab + TILEF * 4;
        #pragma unroll
        for (int p = 0; p < 4; p++) {
            const uint32_t off = (uint32_t)((p * 32 + lrow) * LDSR + lcol) * 4;
            cp16(ab + off, aSrc + (size_t)(p * 32) * C + k0);
            cp16(bb + off, bSrc + (size_t)(p * 32) * C + k0);
        }
    };

    // ldmatrix lane offsets (bytes, within tile)
    uint32_t aoff[4], boff[2];
    #pragma unroll
    for (int mf = 0; mf < 4; mf++) {
        const int row = wm * 64 + mf * 16 + (lg & 1) * 8 + lr8;
        aoff[mf] = (uint32_t)(row * LDSR + (lg >> 1) * 4) * 4;
    }
    #pragma unroll
    for (int p = 0; p < 2; p++) {
        const int row = wn * 32 + p * 16 + (lg >> 1) * 8 + lr8;
        boff[p] = (uint32_t)(row * LDSR + (lg & 1) * 4) * 4;
    }

    issue(0); CP_COMMIT();
    issue(1); CP_COMMIT();

    for (int s = 0; s < 16; s++) {
        CP_WAIT1();
        __syncthreads();
        if (s + 2 < 16) issue(s + 2);
        CP_COMMIT();

        const uint32_t ab = smb + (uint32_t)((s % GSTAGES) * STAGEF) * 4;
        const uint32_t bb = ab + TILEF * 4;
        #pragma unroll
        for (int ks = 0; ks < 4; ks++) {
            const uint32_t kb = ks * 32;           // 8 floats
            uint32_t af[4][4], bf[2][4];
            #pragma unroll
            for (int mf = 0; mf < 4; mf++)
                LDM4(af[mf][0], af[mf][1], af[mf][2], af[mf][3], ab + aoff[mf] + kb);
            #pragma unroll
            for (int p = 0; p < 2; p++)
                LDM4(bf[p][0], bf[p][1], bf[p][2], bf[p][3], bb + boff[p] + kb);
            #pragma unroll
            for (int mf = 0; mf < 4; mf++)
                #pragma unroll
                for (int p = 0; p < 2; p++) {
                    mma_tf32(acc[mf][2 * p],     af[mf], &bf[p][0]);
                    mma_tf32(acc[mf][2 * p + 1], af[mf], &bf[p][2]);
                }
        }
    }

    // Epilogue
    #pragma unroll
    for (int nf = 0; nf < 4; nf++) {
        const int j = n0 + wn * 32 + nf * 8 + 2 * tig;
        const float b0 = bias[j], b1 = bias[j + 1];
        #pragma unroll
        for (int mf = 0; mf < 4; mf++) {
            const int mrow0 = m0 + wm * 64 + mf * 16 + gid;
            #pragma unroll
            for (int half = 0; half < 2; half++) {
                const int m = mrow0 + half * 8;
                float vx = acc[mf][nf][half * 2 + 0] + b0;
                float vy = acc[mf][nf][half * 2 + 1] + b1;
                if (mode == 0) {
                    vx = rndtf(vx); vy = rndtf(vy);
                    const int kind = j >> 9;
                    const int hh = (j >> 6) & 7;
                    const int dd = j & 63;
                    const int bb2 = m >> 8;
                    const int tt = m & 255;
                    if (kind == 2) {   // V transposed: [b,h,d,t]
                        float* dst = g_v + (((size_t)(bb2 * H + hh)) * D + dd) * T + tt;
                        dst[0] = vx;
                        dst[T] = vy;
                    } else {
                        float* bufp = (kind == 0) ? g_q : g_k;
                        float* dst = bufp + (((size_t)(bb2 * H + hh)) * T + tt) * D + dd;
                        *(float2*)dst = make_float2(vx, vy);
                    }
                } else {
                    float* dst = outp + (size_t)m * C + j;
                    *(float2*)dst = make_float2(vx, vy);
                }
            }
        }
    }
}

// ---------------------------------------------------------------------------
// Tensor-core attention: one block per (qtile 64 rows, h, b), 8 warps.
// Phase 1: S = Q K^T via mma (warp grid 2m x 4n), raw scores -> St[i][s]
// Phase 2: softmax rows (scale folded into exp)
// Phase 3: O = P V via mma (warp grid 2m x 4n over d), /l, -> g_attn rounded
// ---------------------------------------------------------------------------
constexpr int QSTR = 68;    // Q/K row stride (floats)
constexpr int SSTR = 260;   // St/Vt row stride (floats)
constexpr int AQ_OFF = 0;                       // Qs[64][68]
constexpr int AK_OFF = AQ_OFF + 64 * QSTR;      // Ks[256][68]
constexpr int AV_OFF = AK_OFF + 256 * QSTR;     // Vt[64][260]
constexpr int AS_OFF = AV_OFF + 64 * SSTR;      // St[64][260]
constexpr int AL_OFF = AS_OFF + 64 * SSTR;      // l[64]
constexpr int ATTN_FLOATS = AL_OFF + 64;
constexpr size_t SMEM_ATTN = (size_t)ATTN_FLOATS * 4;   // 220,672 B

__global__ void __launch_bounds__(256) attn_kernel()
{
    extern __shared__ float smf[];
    const uint32_t smb = smem_u32(smf);
    float* Qs = smf + AQ_OFF;
    float* Ks = smf + AK_OFF;
    float* Vt = smf + AV_OFF;
    float* St = smf + AS_OFF;
    float* lr_ = smf + AL_OFF;

    const int qt  = blockIdx.x;            // 0..3
    const int hh  = blockIdx.y;
    const int bb  = blockIdx.z;
    const int tid = threadIdx.x;
    const int wid = tid >> 5;
    const int lid = tid & 31;
    const int gid = lid >> 2, tig = lid & 3;
    const int lg = lid >> 3, lr8 = lid & 7;
    const int wm = wid & 1;                // 32 q-rows each
    const int wn = wid >> 1;               // 4 n-groups
    const int S_lim = (qt + 1) * 64;
    const int t0 = qt * 64;

    const float* qp = g_q + ((size_t)(bb * H + hh)) * T * D;
    const float* kp = g_k + ((size_t)(bb * H + hh)) * T * D;
    const float* vp = g_v + ((size_t)(bb * H + hh)) * D * T;   // [d][t]

    // ---- loads ----
    for (int idx = tid; idx < 64 * 16; idx += 256) {
        int i = idx >> 4, dg = (idx & 15) * 4;
        *(float4*)&Qs[i * QSTR + dg] = *(const float4*)(qp + (size_t)(t0 + i) * D + dg);
    }
    for (int idx = tid; idx < S_lim * 16; idx += 256) {
        int s = idx >> 4, dg = (idx & 15) * 4;
        *(float4*)&Ks[s * QSTR + dg] = *(const float4*)(kp + (size_t)s * D + dg);
    }
    {
        const int sq = S_lim >> 2;         // float4s per Vt row
        for (int idx = tid; idx < 64 * sq; idx += 256) {
            int d = idx / sq, sg = (idx - d * sq) * 4;
            *(float4*)&Vt[d * SSTR + sg] = *(const float4*)(vp + (size_t)d * T + sg);
        }
    }
    __syncthreads();

    // ---- Phase 1: S = Q K^T ----
    {
        const int NW = S_lim >> 2;         // per-warp n width (16..64)
        const int nfmax = NW >> 3;         // 2..8
        const int npair = nfmax >> 1;      // 1..4
        const int t_hi = t0 + wm * 32 + 31;

        float acc[2][8][4];
        #pragma unroll
        for (int i = 0; i < 2; i++)
            #pragma unroll
            for (int j = 0; j < 8; j++)
                #pragma unroll
                for (int q = 0; q < 4; q++) acc[i][j][q] = 0.f;

        uint32_t qoff[2];
        #pragma unroll
        for (int mf = 0; mf < 2; mf++) {
            const int row = wm * 32 + mf * 16 + (lg & 1) * 8 + lr8;
            qoff[mf] = smb + (uint32_t)(AQ_OFF + row * QSTR + (lg >> 1) * 4) * 4;
        }

        #pragma unroll
        for (int ks = 0; ks < 8; ks++) {
            const uint32_t kb = ks * 32;
            uint32_t af[2][4];
            #pragma unroll
            for (int mf = 0; mf < 2; mf++)
                LDM4(af[mf][0], af[mf][1], af[mf][2], af[mf][3], qoff[mf] + kb);
            #pragma unroll
            for (int p = 0; p < 4; p++) {
                if (p >= npair) break;
                const int n_lo = wn * NW + p * 16;
                if (n_lo > t_hi) continue;            // fully-masked pair
                const int rowk = n_lo + (lg >> 1) * 8 + lr8;
                uint32_t bf[4];
                LDM4(bf[0], bf[1], bf[2], bf[3],
                     smb + (uint32_t)(AK_OFF + rowk * QSTR + (lg & 1) * 4) * 4 + kb);
                #pragma unroll
                for (int mf = 0; mf < 2; mf++) {
                    mma_tf32(acc[mf][2 * p],     af[mf], &bf[0]);
                    if (n_lo + 8 <= t_hi)
                        mma_tf32(acc[mf][2 * p + 1], af[mf], &bf[2]);
                }
            }
        }
        // store raw scores St[i][s]
        #pragma unroll
        for (int mf = 0; mf < 2; mf++) {
            const int row = wm * 32 + mf * 16 + gid;
            #pragma unroll
            for (int nf = 0; nf < 8; nf++) {
                if (nf >= nfmax) break;
                const int col = wn * NW + nf * 8 + 2 * tig;
                *(float2*)&St[row * SSTR + col] =
                    make_float2(acc[mf][nf][0], acc[mf][nf][1]);
                *(float2*)&St[(row + 8) * SSTR + col] =
                    make_float2(acc[mf][nf][2], acc[mf][nf][3]);
            }
        }
    }
    __syncthreads();

    // ---- Phase 2: softmax per row ----
    {
        const int i = tid >> 2;
        const int p = tid & 3;
        const int tg = t0 + i;
        float mx = -3.4e38f;
        for (int s = p; s <= tg; s += 4) mx = fmaxf(mx, St[i * SSTR + s]);
        mx = fmaxf(mx, __shfl_xor_sync(0xffffffffu, mx, 1));
        mx = fmaxf(mx, __shfl_xor_sync(0xffffffffu, mx, 2));
        float sum = 0.f;
        for (int s = p; s < S_lim; s += 4) {
            float v = St[i * SSTR + s];
            float e = (s <= tg) ? __expf((v - mx) * 0.125f) : 0.f;
            St[i * SSTR + s] = e;
            sum += e;
        }
        sum += __shfl_xor_sync(0xffffffffu, sum, 1);
        sum += __shfl_xor_sync(0xffffffffu, sum, 2);
        if (p == 0) lr_[i] = sum;
    }
    __syncthreads();

    // ---- Phase 3: O = P V ----
    {
        float acc[2][2][4];
        #pragma unroll
        for (int i = 0; i < 2; i++)
            #pragma unroll
            for (int j = 0; j < 2; j++)
                #pragma unroll
                for (int q = 0; q < 4; q++) acc[i][j][q] = 0.f;

        uint32_t soff[2];
        #pragma unroll
        for (int mf = 0; mf < 2; mf++) {
            const int row = wm * 32 + mf * 16 + (lg & 1) * 8 + lr8;
            soff[mf] = smb + (uint32_t)(AS_OFF + row * SSTR + (lg >> 1) * 4) * 4;
        }
        const int rowv = wn * 16 + (lg >> 1) * 8 + lr8;
        const uint32_t voff = smb + (uint32_t)(AV_OFF + rowv * SSTR + (lg & 1) * 4) * 4;

        const int kmax = min(S_lim, t0 + wm * 32 + 32);   // rows beyond have P=0
        const int kst = kmax >> 3;
        for (int ks = 0; ks < kst; ks++) {
            const uint32_t kb = ks * 32;
            uint32_t af[2][4], bf[4];
            LDM4(bf[0], bf[1], bf[2], bf[3], voff + kb);
            #pragma unroll
            for (int mf = 0; mf < 2; mf++) {
                LDM4(af[mf][0], af[mf][1], af[mf][2], af[mf][3], soff[mf] + kb);
                mma_tf32(acc[mf][0], af[mf], &bf[0]);
                mma_tf32(acc[mf][1], af[mf], &bf[2]);
            }
        }

        // epilogue: /l, round to tf32, write g_attn
        #pragma unroll
        for (int mf = 0; mf < 2; mf++) {
            const int row0 = wm * 32 + mf * 16 + gid;
            #pragma unroll
            for (int nf = 0; nf < 2; nf++) {
                const int col = wn * 16 + nf * 8 + 2 * tig;
                #pragma unroll
                for (int half = 0; half < 2; half++) {
                    const int i = row0 + half * 8;
                    const float inv = 1.f / lr_[i];
                    float2 v;
                    v.x = rndtf(acc[mf][nf][half * 2 + 0] * inv);
                    v.y = rndtf(acc[mf][nf][half * 2 + 1] * inv);
                    *(float2*)(g_attn + ((size_t)bb * T + t0 + i) * C + hh * D + col) = v;
                }
            }
        }
    }
}

// ---------------------------------------------------------------------------
extern "C" void kernel_launch(void* const* d_in, const int* in_sizes, int n_in,
                              void* d_out, int out_size)
{
    const float* x  = (const float*)d_in[0];
    const float* wq = (const float*)d_in[1];
    const float* wk = (const float*)d_in[2];
    const float* wv = (const float*)d_in[3];
    const float* bq = (const float*)d_in[4];
    const float* bk = (const float*)d_in[5];
    const float* bv = (const float*)d_in[6];
    const float* wo = (const float*)d_in[7];
    const float* bo = (const float*)d_in[8];
    float* out = (float*)d_out;

    cudaFuncSetAttribute(attn_kernel, cudaFuncAttributeMaxDynamicSharedMemorySize,
                         (int)SMEM_ATTN);
    cudaFuncSetAttribute(gemm_mma_kernel, cudaFuncAttributeMaxDynamicSharedMemorySize,
                         SMEM_GEMM_BYTES);

    cvt_x_kernel<<<(M * C / 4) / 256, 256>>>((const float4*)x);
    transpose_qkv_kernel<<<dim3(16, 2, 24), dim3(32, 8)>>>(wq, wk, wv);
    transpose_wo_kernel<<<dim3(16, 16), dim3(32, 8)>>>(wo);
    bias_concat_kernel<<<6, 256>>>(bq, bk, bv);

    gemm_mma_kernel<<<dim3(N3 / 128, M / 128), 256, SMEM_GEMM_BYTES>>>(nullptr, nullptr, 0);
    attn_kernel<<<dim3(T / 64, H, B), 256, SMEM_ATTN>>>();
    gemm_mma_kernel<<<dim3(C / 128, M / 128), 256, SMEM_GEMM_BYTES>>>(bo, out, 1);
}

// round 10
// speedup vs baseline: 3.1791x; 1.0971x over previous
#include <cuda_runtime.h>
#include <cuda.h>
#include <math.h>
#include <cstdint>

// Problem constants
constexpr int B = 64, T = 256, C = 512, H = 8, D = 64;
constexpr int M = B * T;        // 16384 rows
constexpr int N3 = 3 * H * D;   // 1536 qkv columns

// Scratch (allocation-free: __device__ globals)
__device__ float g_q[(size_t)B * H * T * D];     // [B,H,T,D]   (tf32-rounded)
__device__ float g_k[(size_t)B * H * T * D];     // [B,H,T,D]   (tf32-rounded)
__device__ float g_v[(size_t)B * H * D * T];     // [B,H,D,T] TRANSPOSED (tf32-rounded)
__device__ float g_attn[(size_t)M * C];          // [B*T, H*D]  (tf32-rounded)
__device__ float g_wt[(size_t)N3 * C];           // K-major qkv weights (tf32-rounded)
__device__ float g_wot[(size_t)C * C];           // K-major wo (tf32-rounded)
__device__ float g_bcat[N3];                     // concatenated qkv bias (fp32)
__device__ float g_xr[(size_t)M * C];            // tf32-rounded x

// ---------------------------------------------------------------------------
// Helpers
// ---------------------------------------------------------------------------
__device__ __forceinline__ uint32_t f2tf32(float v) {
    uint32_t u;
    asm("cvt.rna.tf32.f32 %0, %1;" : "=r"(u) : "f"(v));
    return u;
}
__device__ __forceinline__ float rndtf(float v) { return __uint_as_float(f2tf32(v)); }

__device__ __forceinline__ float ex2f(float x) {
    float y;
    asm("ex2.approx.f32 %0, %1;" : "=f"(y) : "f"(x));
    return y;
}
__device__ __forceinline__ uint32_t smem_u32(const void* p) {
    uint32_t a;
    asm("{ .reg .u64 t; cvta.to.shared.u64 t, %1; cvt.u32.u64 %0, t; }" : "=r"(a) : "l"(p));
    return a;
}
__device__ __forceinline__ void mma_tf32(float* c, const uint32_t* a, const uint32_t* b) {
    asm volatile(
        "mma.sync.aligned.m16n8k8.row.col.f32.tf32.tf32.f32 "
        "{%0,%1,%2,%3}, {%4,%5,%6,%7}, {%8,%9}, {%0,%1,%2,%3};"
        : "+f"(c[0]), "+f"(c[1]), "+f"(c[2]), "+f"(c[3])
        : "r"(a[0]), "r"(a[1]), "r"(a[2]), "r"(a[3]), "r"(b[0]), "r"(b[1]));
}
#define LDM4(r0, r1, r2, r3, addr)                                              \
    asm volatile("ldmatrix.sync.aligned.m8n8.x4.shared.b16 {%0,%1,%2,%3}, [%4];" \
                 : "=r"(r0), "=r"(r1), "=r"(r2), "=r"(r3) : "r"(addr))

__device__ __forceinline__ void cp16(uint32_t dst, const void* src) {
    asm volatile("cp.async.cg.shared.global [%0], [%1], 16;" :: "r"(dst), "l"(src));
}
#define CP_COMMIT() asm volatile("cp.async.commit_group;" ::: "memory")
#define CP_WAIT1()  asm volatile("cp.async.wait_group 1;" ::: "memory")

// ---------------------------------------------------------------------------
// Fused prep kernel: block-role dispatch
//   [0, NCVT)            cvt x -> g_xr (tf32-rounded)
//   [NCVT, +768)         transpose qkv weights -> g_wt
//   [.., +256)           transpose wo -> g_wot
//   [.., +6)             bias concat
// ---------------------------------------------------------------------------
constexpr int NCVT = (M * C / 4) / 256;      // 8192
constexpr int NTQ  = 16 * 2 * 24;            // 768
constexpr int NTW  = 16 * 16;                // 256
constexpr int PREP_BLOCKS = NCVT + NTQ + NTW + 6;

__global__ void __launch_bounds__(256) prep_kernel(
    const float4* __restrict__ x,
    const float* __restrict__ wq, const float* __restrict__ wk,
    const float* __restrict__ wv, const float* __restrict__ wo,
    const float* __restrict__ bq, const float* __restrict__ bk,
    const float* __restrict__ bv)
{
    __shared__ float t[32][33];
    const int blk = blockIdx.x;
    const int tid = threadIdx.x;

    if (blk < NCVT) {
        int i = blk * 256 + tid;
        float4 v = x[i];
        v.x = rndtf(v.x); v.y = rndtf(v.y); v.z = rndtf(v.z); v.w = rndtf(v.w);
        ((float4*)g_xr)[i] = v;
        return;
    }
    const int tx = tid & 31, ty = tid >> 5;
    if (blk < NCVT + NTQ) {
        const int r = blk - NCVT;            // r = bx + by*16 + bz*32
        const int bx = r & 15, by = (r >> 4) & 1, bz = r >> 5;
        const int kind = bz >> 3, h = bz & 7;
        const float* src = ((kind == 0) ? wq : (kind == 1) ? wk : wv) + (size_t)h * C * D;
        const int c0 = bx * 32, d0 = by * 32;
        #pragma unroll
        for (int i = 0; i < 32; i += 8)
            t[ty + i][tx] = src[(size_t)(c0 + ty + i) * D + d0 + tx];
        __syncthreads();
        float* dst = g_wt + (size_t)(kind * 512 + h * 64) * C;
        #pragma unroll
        for (int i = 0; i < 32; i += 8)
            dst[(size_t)(d0 + ty + i) * C + c0 + tx] = rndtf(t[tx][ty + i]);
        return;
    }
    if (blk < NCVT + NTQ + NTW) {
        const int r = blk - NCVT - NTQ;
        const int n0 = (r & 15) * 32, k0 = (r >> 4) * 32;
        #pragma unroll
        for (int i = 0; i < 32; i += 8)
            t[ty + i][tx] = wo[(size_t)(k0 + ty + i) * C + n0 + tx];
        __syncthreads();
        #pragma unroll
        for (int i = 0; i < 32; i += 8)
            g_wot[(size_t)(n0 + ty + i) * C + k0 + tx] = rndtf(t[tx][ty + i]);
        return;
    }
    {
        const int idx = (blk - NCVT - NTQ - NTW) * 256 + tid;
        if (idx < N3) {
            int kind = idx >> 9, i = idx & 511;
            g_bcat[idx] = (kind == 0) ? bq[i] : (kind == 1) ? bk[i] : bv[i];
        }
    }
}

// ---------------------------------------------------------------------------
// mma.sync tf32 GEMM, cp.async 3-stage + ldmatrix (unchanged from R9).
// ---------------------------------------------------------------------------
constexpr int LDSR = 36;
constexpr int TILEF = 128 * LDSR;
constexpr int STAGEF = 2 * TILEF;
constexpr int GSTAGES = 3;
constexpr int SMEM_GEMM_BYTES = GSTAGES * STAGEF * 4;   // 110,592 B

__global__ void __launch_bounds__(256, 2) gemm_mma_kernel(
    const float* __restrict__ bo_in, float* __restrict__ outp, int mode)
{
    extern __shared__ float sm[];
    const uint32_t smb = smem_u32(sm);
    const int tid = threadIdx.x;
    const int wid = tid >> 5;
    const int lid = tid & 31;
    const int gid = lid >> 2, tig = lid & 3;
    const int lg = lid >> 3, lr8 = lid & 7;
    const int wm = wid & 1;
    const int wn = wid >> 1;

    const float* A    = (mode == 0) ? g_xr : g_attn;
    const float* Bt   = (mode == 0) ? g_wt : g_wot;
    const float* bias = (mode == 0) ? g_bcat : bo_in;

    const int n0 = blockIdx.x * 128;
    const int m0 = blockIdx.y * 128;

    float acc[4][4][4];
    #pragma unroll
    for (int i = 0; i < 4; i++)
        #pragma unroll
        for (int j = 0; j < 4; j++)
            #pragma unroll
            for (int q = 0; q < 4; q++) acc[i][j][q] = 0.f;

    const int lrow = tid >> 3;
    const int lcol = (tid & 7) * 4;
    const float* aSrc = A  + (size_t)(m0 + lrow) * C + lcol;
    const float* bSrc = Bt + (size_t)(n0 + lrow) * C + lcol;

    auto issue = [&](int s) {
        const int k0 = s * 32;
        const uint32_t ab = smb + (uint32_t)((s % GSTAGES) * STAGEF) * 4;
        const uint32_t bb = ab + TILEF * 4;
        #pragma unroll
        for (int p = 0; p < 4; p++) {
            const uint32_t off = (uint32_t)((p * 32 + lrow) * LDSR + lcol) * 4;
            cp16(ab + off, aSrc + (size_t)(p * 32) * C + k0);
            cp16(bb + off, bSrc + (size_t)(p * 32) * C + k0);
        }
    };

    uint32_t aoff[4], boff[2];
    #pragma unroll
    for (int mf = 0; mf < 4; mf++) {
        const int row = wm * 64 + mf * 16 + (lg & 1) * 8 + lr8;
        aoff[mf] = (uint32_t)(row * LDSR + (lg >> 1) * 4) * 4;
    }
    #pragma unroll
    for (int p = 0; p < 2; p++) {
        const int row = wn * 32 + p * 16 + (lg >> 1) * 8 + lr8;
        boff[p] = (uint32_t)(row * LDSR + (lg & 1) * 4) * 4;
    }

    issue(0); CP_COMMIT();
    issue(1); CP_COMMIT();

    for (int s = 0; s < 16; s++) {
        CP_WAIT1();
        __syncthreads();
        if (s + 2 < 16) issue(s + 2);
        CP_COMMIT();

        const uint32_t ab = smb + (uint32_t)((s % GSTAGES) * STAGEF) * 4;
        const uint32_t bb = ab + TILEF * 4;
        #pragma unroll
        for (int ks = 0; ks < 4; ks++) {
            const uint32_t kb = ks * 32;
            uint32_t af[4][4], bf[2][4];
            #pragma unroll
            for (int mf = 0; mf < 4; mf++)
                LDM4(af[mf][0], af[mf][1], af[mf][2], af[mf][3], ab + aoff[mf] + kb);
            #pragma unroll
            for (int p = 0; p < 2; p++)
                LDM4(bf[p][0], bf[p][1], bf[p][2], bf[p][3], bb + boff[p] + kb);
            #pragma unroll
            for (int mf = 0; mf < 4; mf++)
                #pragma unroll
                for (int p = 0; p < 2; p++) {
                    mma_tf32(acc[mf][2 * p],     af[mf], &bf[p][0]);
                    mma_tf32(acc[mf][2 * p + 1], af[mf], &bf[p][2]);
                }
        }
    }

    #pragma unroll
    for (int nf = 0; nf < 4; nf++) {
        const int j = n0 + wn * 32 + nf * 8 + 2 * tig;
        const float b0 = bias[j], b1 = bias[j + 1];
        #pragma unroll
        for (int mf = 0; mf < 4; mf++) {
            const int mrow0 = m0 + wm * 64 + mf * 16 + gid;
            #pragma unroll
            for (int half = 0; half < 2; half++) {
                const int m = mrow0 + half * 8;
                float vx = acc[mf][nf][half * 2 + 0] + b0;
                float vy = acc[mf][nf][half * 2 + 1] + b1;
                if (mode == 0) {
                    vx = rndtf(vx); vy = rndtf(vy);
                    const int kind = j >> 9;
                    const int hh = (j >> 6) & 7;
                    const int dd = j & 63;
                    const int bb2 = m >> 8;
                    const int tt = m & 255;
                    if (kind == 2) {   // V transposed: [b,h,d,t]
                        float* dst = g_v + (((size_t)(bb2 * H + hh)) * D + dd) * T + tt;
                        dst[0] = vx;
                        dst[T] = vy;
                    } else {
                        float* bufp = (kind == 0) ? g_q : g_k;
                        float* dst = bufp + (((size_t)(bb2 * H + hh)) * T + tt) * D + dd;
                        *(float2*)dst = make_float2(vx, vy);
                    }
                } else {
                    float* dst = outp + (size_t)m * C + j;
                    *(float2*)dst = make_float2(vx, vy);
                }
            }
        }
    }
}

// ---------------------------------------------------------------------------
// Tensor-core attention with register softmax (FA2-style partials).
// One block per (qtile 64 rows, h, b), 8 warps (wm 2 x wn 4).
// Phase 1: S = Q K^T (mma), causal mask in regs, per-warp row max via shfl,
//          cross-warp (wn) max via 4x64 smem exchange, exp in regs,
//          store P to St once, partial sums -> 4x64 smem.
// Phase 2: O = P V (mma over d), /l from summed partials, -> g_attn rounded.
// ---------------------------------------------------------------------------
constexpr int QSTR = 68;    // Q/K row stride (floats)
constexpr int SSTR = 260;   // St/Vt row stride (floats)
constexpr int AQ_OFF = 0;                       // Qs[64][68]
constexpr int AK_OFF = AQ_OFF + 64 * QSTR;      // Ks[256][68]
constexpr int AV_OFF = AK_OFF + 256 * QSTR;     // Vt[64][260]
constexpr int AS_OFF = AV_OFF + 64 * SSTR;      // St[64][260] (P)
constexpr int APM_OFF = AS_OFF + 64 * SSTR;     // pmax[4][64]
constexpr int APS_OFF = APM_OFF + 256;          // psum[4][64]
constexpr int ATTN_FLOATS = APS_OFF + 256;
constexpr size_t SMEM_ATTN = (size_t)ATTN_FLOATS * 4;   // 222,208 B

__global__ void __launch_bounds__(256) attn_kernel()
{
    extern __shared__ float smf[];
    const uint32_t smb = smem_u32(smf);
    float* Qs = smf + AQ_OFF;
    float* Ks = smf + AK_OFF;
    float* Vt = smf + AV_OFF;
    float* St = smf + AS_OFF;
    float* pmx = smf + APM_OFF;
    float* psm = smf + APS_OFF;

    const int qt  = blockIdx.x;            // 0..3
    const int hh  = blockIdx.y;
    const int bb  = blockIdx.z;
    const int tid = threadIdx.x;
    const int wid = tid >> 5;
    const int lid = tid & 31;
    const int gid = lid >> 2, tig = lid & 3;
    const int lg = lid >> 3, lr8 = lid & 7;
    const int wm = wid & 1;                // 32 q-rows each
    const int wn = wid >> 1;               // 4 col-groups
    const int S_lim = (qt + 1) * 64;
    const int t0 = qt * 64;

    const float* qp = g_q + ((size_t)(bb * H + hh)) * T * D;
    const float* kp = g_k + ((size_t)(bb * H + hh)) * T * D;
    const float* vp = g_v + ((size_t)(bb * H + hh)) * D * T;   // [d][t]

    // ---- loads ----
    for (int idx = tid; idx < 64 * 16; idx += 256) {
        int i = idx >> 4, dg = (idx & 15) * 4;
        *(float4*)&Qs[i * QSTR + dg] = *(const float4*)(qp + (size_t)(t0 + i) * D + dg);
    }
    for (int idx = tid; idx < S_lim * 16; idx += 256) {
        int s = idx >> 4, dg = (idx & 15) * 4;
        *(float4*)&Ks[s * QSTR + dg] = *(const float4*)(kp + (size_t)s * D + dg);
    }
    {
        const int sq = S_lim >> 2;
        for (int idx = tid; idx < 64 * sq; idx += 256) {
            int d = idx / sq, sg = (idx - d * sq) * 4;
            *(float4*)&Vt[d * SSTR + sg] = *(const float4*)(vp + (size_t)d * T + sg);
        }
    }
    __syncthreads();

    // ---- Phase 1: S = Q K^T + register softmax ----
    const int NW = S_lim >> 2;         // per-warp col width (16..64)
    const int nfmax = NW >> 3;         // 2..8
    {
        const int npair = nfmax >> 1;
        const int t_hi = t0 + wm * 32 + 31;

        float acc[2][8][4];
        #pragma unroll
        for (int i = 0; i < 2; i++)
            #pragma unroll
            for (int j = 0; j < 8; j++)
                #pragma unroll
                for (int q = 0; q < 4; q++) acc[i][j][q] = 0.f;

        uint32_t qoff[2];
        #pragma unroll
        for (int mf = 0; mf < 2; mf++) {
            const int row = wm * 32 + mf * 16 + (lg & 1) * 8 + lr8;
            qoff[mf] = smb + (uint32_t)(AQ_OFF + row * QSTR + (lg >> 1) * 4) * 4;
        }

        #pragma unroll
        for (int ks = 0; ks < 8; ks++) {
            const uint32_t kb = ks * 32;
            uint32_t af[2][4];
            #pragma unroll
            for (int mf = 0; mf < 2; mf++)
                LDM4(af[mf][0], af[mf][1], af[mf][2], af[mf][3], qoff[mf] + kb);
            #pragma unroll
            for (int p = 0; p < 4; p++) {
                if (p >= npair) break;
                const int n_lo = wn * NW + p * 16;
                if (n_lo > t_hi) continue;
                const int rowk = n_lo + (lg >> 1) * 8 + lr8;
                uint32_t bf[4];
                LDM4(bf[0], bf[1], bf[2], bf[3],
                     smb + (uint32_t)(AK_OFF + rowk * QSTR + (lg & 1) * 4) * 4 + kb);
                #pragma unroll
                for (int mf = 0; mf < 2; mf++) {
                    mma_tf32(acc[mf][2 * p],     af[mf], &bf[0]);
                    if (n_lo + 8 <= t_hi)
                        mma_tf32(acc[mf][2 * p + 1], af[mf], &bf[2]);
                }
            }
        }

        // causal mask in registers + per-warp row-partial max
        float wmax[2][2];
        #pragma unroll
        for (int mf = 0; mf < 2; mf++) {
            const int r0 = wm * 32 + mf * 16 + gid;       // local row (half 0)
            const int tg0 = t0 + r0, tg1 = tg0 + 8;
            wmax[mf][0] = -1e30f; wmax[mf][1] = -1e30f;
            #pragma unroll
            for (int nf = 0; nf < 8; nf++) {
                if (nf >= nfmax) break;
                const int s0 = wn * NW + nf * 8 + 2 * tig;
                float* a = acc[mf][nf];
                a[0] = (s0     <= tg0) ? a[0] : -1e30f;
                a[1] = (s0 + 1 <= tg0) ? a[1] : -1e30f;
                a[2] = (s0     <= tg1) ? a[2] : -1e30f;
                a[3] = (s0 + 1 <= tg1) ? a[3] : -1e30f;
                wmax[mf][0] = fmaxf(wmax[mf][0], fmaxf(a[0], a[1]));
                wmax[mf][1] = fmaxf(wmax[mf][1], fmaxf(a[2], a[3]));
            }
            #pragma unroll
            for (int hf = 0; hf < 2; hf++) {
                wmax[mf][hf] = fmaxf(wmax[mf][hf], __shfl_xor_sync(0xffffffffu, wmax[mf][hf], 1));
                wmax[mf][hf] = fmaxf(wmax[mf][hf], __shfl_xor_sync(0xffffffffu, wmax[mf][hf], 2));
            }
            if (tig == 0) {
                pmx[wn * 64 + r0]     = wmax[mf][0];
                pmx[wn * 64 + r0 + 8] = wmax[mf][1];
            }
        }
        __syncthreads();

        // global row max, exp, store P, partial sums
        const float C1 = 0.18033688011112042f;   // 0.125 * log2(e)
        #pragma unroll
        for (int mf = 0; mf < 2; mf++) {
            const int r0 = wm * 32 + mf * 16 + gid;
            float gm0 = fmaxf(fmaxf(pmx[r0], pmx[64 + r0]),
                              fmaxf(pmx[128 + r0], pmx[192 + r0]));
            float gm1 = fmaxf(fmaxf(pmx[r0 + 8], pmx[64 + r0 + 8]),
                              fmaxf(pmx[128 + r0 + 8], pmx[192 + r0 + 8]));
            float ps0 = 0.f, ps1 = 0.f;
            #pragma unroll
            for (int nf = 0; nf < 8; nf++) {
                if (nf >= nfmax) break;
                const int s0 = wn * NW + nf * 8 + 2 * tig;
                float* a = acc[mf][nf];
                float e0 = ex2f((a[0] - gm0) * C1);
                float e1 = ex2f((a[1] - gm0) * C1);
                float e2 = ex2f((a[2] - gm1) * C1);
                float e3 = ex2f((a[3] - gm1) * C1);
                ps0 += e0 + e1;
                ps1 += e2 + e3;
                *(float2*)&St[r0 * SSTR + s0]       = make_float2(e0, e1);
                *(float2*)&St[(r0 + 8) * SSTR + s0] = make_float2(e2, e3);
            }
            ps0 += __shfl_xor_sync(0xffffffffu, ps0, 1);
            ps0 += __shfl_xor_sync(0xffffffffu, ps0, 2);
            ps1 += __shfl_xor_sync(0xffffffffu, ps1, 1);
            ps1 += __shfl_xor_sync(0xffffffffu, ps1, 2);
            if (tig == 0) {
                psm[wn * 64 + r0]     = ps0;
                psm[wn * 64 + r0 + 8] = ps1;
            }
        }
    }
    __syncthreads();

    // ---- Phase 2: O = P V ----
    {
        float acc[2][2][4];
        #pragma unroll
        for (int i = 0; i < 2; i++)
            #pragma unroll
            for (int j = 0; j < 2; j++)
                #pragma unroll
                for (int q = 0; q < 4; q++) acc[i][j][q] = 0.f;

        uint32_t soff[2];
        #pragma unroll
        for (int mf = 0; mf < 2; mf++) {
            const int row = wm * 32 + mf * 16 + (lg & 1) * 8 + lr8;
            soff[mf] = smb + (uint32_t)(AS_OFF + row * SSTR + (lg >> 1) * 4) * 4;
        }
        const int rowv = wn * 16 + (lg >> 1) * 8 + lr8;
        const uint32_t voff = smb + (uint32_t)(AV_OFF + rowv * SSTR + (lg & 1) * 4) * 4;

        const int kmax = min(S_lim, t0 + wm * 32 + 32);   // rows beyond have P=0
        const int kst = kmax >> 3;
        for (int ks = 0; ks < kst; ks++) {
            const uint32_t kb = ks * 32;
            uint32_t af[2][4], bf[4];
            LDM4(bf[0], bf[1], bf[2], bf[3], voff + kb);
            #pragma unroll
            for (int mf = 0; mf < 2; mf++) {
                LDM4(af[mf][0], af[mf][1], af[mf][2], af[mf][3], soff[mf] + kb);
                mma_tf32(acc[mf][0], af[mf], &bf[0]);
                mma_tf32(acc[mf][1], af[mf], &bf[2]);
            }
        }

        // epilogue: /l, round to tf32, write g_attn
        #pragma unroll
        for (int mf = 0; mf < 2; mf++) {
            const int row0 = wm * 32 + mf * 16 + gid;
            #pragma unroll
            for (int half = 0; half < 2; half++) {
                const int i = row0 + half * 8;
                const float l = psm[i] + psm[64 + i] + psm[128 + i] + psm[192 + i];
                const float inv = 1.f / l;
                #pragma unroll
                for (int nf = 0; nf < 2; nf++) {
                    const int col = wn * 16 + nf * 8 + 2 * tig;
                    float2 v;
                    v.x = rndtf(acc[mf][nf][half * 2 + 0] * inv);
                    v.y = rndtf(acc[mf][nf][half * 2 + 1] * inv);
                    *(float2*)(g_attn + ((size_t)bb * T + t0 + i) * C + hh * D + col) = v;
                }
            }
        }
    }
}

// ---------------------------------------------------------------------------
extern "C" void kernel_launch(void* const* d_in, const int* in_sizes, int n_in,
                              void* d_out, int out_size)
{
    const float* x  = (const float*)d_in[0];
    const float* wq = (const float*)d_in[1];
    const float* wk = (const float*)d_in[2];
    const float* wv = (const float*)d_in[3];
    const float* bq = (const float*)d_in[4];
    const float* bk = (const float*)d_in[5];
    const float* bv = (const float*)d_in[6];
    const float* wo = (const float*)d_in[7];
    const float* bo = (const float*)d_in[8];
    float* out = (float*)d_out;

    cudaFuncSetAttribute(attn_kernel, cudaFuncAttributeMaxDynamicSharedMemorySize,
                         (int)SMEM_ATTN);
    cudaFuncSetAttribute(gemm_mma_kernel, cudaFuncAttributeMaxDynamicSharedMemorySize,
                         SMEM_GEMM_BYTES);

    prep_kernel<<<PREP_BLOCKS, 256>>>((const float4*)x, wq, wk, wv, wo, bq, bk, bv);
    gemm_mma_kernel<<<dim3(N3 / 128, M / 128), 256, SMEM_GEMM_BYTES>>>(nullptr, nullptr, 0);
    attn_kernel<<<dim3(T / 64, H, B), 256, SMEM_ATTN>>>();
    gemm_mma_kernel<<<dim3(C / 128, M / 128), 256, SMEM_GEMM_BYTES>>>(bo, out, 1);
}

// round 11
// speedup vs baseline: 3.6408x; 1.1452x over previous
#include <cuda_runtime.h>
#include <cuda.h>
#include <math.h>
#include <cstdint>

// Problem constants
constexpr int B = 64, T = 256, C = 512, H = 8, D = 64;
constexpr int M = B * T;        // 16384 rows
constexpr int N3 = 3 * H * D;   // 1536 qkv columns

// Scratch (allocation-free: __device__ globals)
__device__ float g_q[(size_t)B * H * T * D];     // [B,H,T,D]   (tf32-rounded)
__device__ float g_k[(size_t)B * H * T * D];     // [B,H,T,D]   (tf32-rounded)
__device__ float g_v[(size_t)B * H * D * T];     // [B,H,D,T] TRANSPOSED (tf32-rounded)
__device__ float g_attn[(size_t)M * C];          // [B*T, H*D]  (tf32-rounded)
__device__ float g_wt[(size_t)N3 * C];           // K-major qkv weights (tf32-rounded)
__device__ float g_wot[(size_t)C * C];           // K-major wo (tf32-rounded)
__device__ float g_bcat[N3];                     // concatenated qkv bias (fp32)
__device__ float g_xr[(size_t)M * C];            // tf32-rounded x

// ---------------------------------------------------------------------------
// Helpers
// ---------------------------------------------------------------------------
__device__ __forceinline__ uint32_t f2tf32(float v) {
    uint32_t u;
    asm("cvt.rna.tf32.f32 %0, %1;" : "=r"(u) : "f"(v));
    return u;
}
__device__ __forceinline__ float rndtf(float v) { return __uint_as_float(f2tf32(v)); }

__device__ __forceinline__ float ex2f(float x) {
    float y;
    asm("ex2.approx.f32 %0, %1;" : "=f"(y) : "f"(x));
    return y;
}
__device__ __forceinline__ uint32_t smem_u32(const void* p) {
    uint32_t a;
    asm("{ .reg .u64 t; cvta.to.shared.u64 t, %1; cvt.u32.u64 %0, t; }" : "=r"(a) : "l"(p));
    return a;
}
__device__ __forceinline__ void mma_tf32(float* c, const uint32_t* a, const uint32_t* b) {
    asm volatile(
        "mma.sync.aligned.m16n8k8.row.col.f32.tf32.tf32.f32 "
        "{%0,%1,%2,%3}, {%4,%5,%6,%7}, {%8,%9}, {%0,%1,%2,%3};"
        : "+f"(c[0]), "+f"(c[1]), "+f"(c[2]), "+f"(c[3])
        : "r"(a[0]), "r"(a[1]), "r"(a[2]), "r"(a[3]), "r"(b[0]), "r"(b[1]));
}
#define LDM4(r0, r1, r2, r3, addr)                                              \
    asm volatile("ldmatrix.sync.aligned.m8n8.x4.shared.b16 {%0,%1,%2,%3}, [%4];" \
                 : "=r"(r0), "=r"(r1), "=r"(r2), "=r"(r3) : "r"(addr))

__device__ __forceinline__ void cp16(uint32_t dst, const void* src) {
    asm volatile("cp.async.cg.shared.global [%0], [%1], 16;" :: "r"(dst), "l"(src));
}
#define CP_COMMIT() asm volatile("cp.async.commit_group;" ::: "memory")
#define CP_WAIT1()  asm volatile("cp.async.wait_group 1;" ::: "memory")

// ---------------------------------------------------------------------------
// Fused prep kernel (unchanged from R10)
// ---------------------------------------------------------------------------
constexpr int NCVT = (M * C / 4) / 256;      // 8192
constexpr int NTQ  = 16 * 2 * 24;            // 768
constexpr int NTW  = 16 * 16;                // 256
constexpr int PREP_BLOCKS = NCVT + NTQ + NTW + 6;

__global__ void __launch_bounds__(256) prep_kernel(
    const float4* __restrict__ x,
    const float* __restrict__ wq, const float* __restrict__ wk,
    const float* __restrict__ wv, const float* __restrict__ wo,
    const float* __restrict__ bq, const float* __restrict__ bk,
    const float* __restrict__ bv)
{
    __shared__ float t[32][33];
    const int blk = blockIdx.x;
    const int tid = threadIdx.x;

    if (blk < NCVT) {
        int i = blk * 256 + tid;
        float4 v = x[i];
        v.x = rndtf(v.x); v.y = rndtf(v.y); v.z = rndtf(v.z); v.w = rndtf(v.w);
        ((float4*)g_xr)[i] = v;
        return;
    }
    const int tx = tid & 31, ty = tid >> 5;
    if (blk < NCVT + NTQ) {
        const int r = blk - NCVT;
        const int bx = r & 15, by = (r >> 4) & 1, bz = r >> 5;
        const int kind = bz >> 3, h = bz & 7;
        const float* src = ((kind == 0) ? wq : (kind == 1) ? wk : wv) + (size_t)h * C * D;
        const int c0 = bx * 32, d0 = by * 32;
        #pragma unroll
        for (int i = 0; i < 32; i += 8)
            t[ty + i][tx] = src[(size_t)(c0 + ty + i) * D + d0 + tx];
        __syncthreads();
        float* dst = g_wt + (size_t)(kind * 512 + h * 64) * C;
        #pragma unroll
        for (int i = 0; i < 32; i += 8)
            dst[(size_t)(d0 + ty + i) * C + c0 + tx] = rndtf(t[tx][ty + i]);
        return;
    }
    if (blk < NCVT + NTQ + NTW) {
        const int r = blk - NCVT - NTQ;
        const int n0 = (r & 15) * 32, k0 = (r >> 4) * 32;
        #pragma unroll
        for (int i = 0; i < 32; i += 8)
            t[ty + i][tx] = wo[(size_t)(k0 + ty + i) * C + n0 + tx];
        __syncthreads();
        #pragma unroll
        for (int i = 0; i < 32; i += 8)
            g_wot[(size_t)(n0 + ty + i) * C + k0 + tx] = rndtf(t[tx][ty + i]);
        return;
    }
    {
        const int idx = (blk - NCVT - NTQ - NTW) * 256 + tid;
        if (idx < N3) {
            int kind = idx >> 9, i = idx & 511;
            g_bcat[idx] = (kind == 0) ? bq[i] : (kind == 1) ? bk[i] : bv[i];
        }
    }
}

// ---------------------------------------------------------------------------
// mma.sync tf32 GEMM (unchanged from R10)
// ---------------------------------------------------------------------------
constexpr int LDSR = 36;
constexpr int TILEF = 128 * LDSR;
constexpr int STAGEF = 2 * TILEF;
constexpr int GSTAGES = 3;
constexpr int SMEM_GEMM_BYTES = GSTAGES * STAGEF * 4;   // 110,592 B

__global__ void __launch_bounds__(256, 2) gemm_mma_kernel(
    const float* __restrict__ bo_in, float* __restrict__ outp, int mode)
{
    extern __shared__ float sm[];
    const uint32_t smb = smem_u32(sm);
    const int tid = threadIdx.x;
    const int wid = tid >> 5;
    const int lid = tid & 31;
    const int gid = lid >> 2, tig = lid & 3;
    const int lg = lid >> 3, lr8 = lid & 7;
    const int wm = wid & 1;
    const int wn = wid >> 1;

    const float* A    = (mode == 0) ? g_xr : g_attn;
    const float* Bt   = (mode == 0) ? g_wt : g_wot;
    const float* bias = (mode == 0) ? g_bcat : bo_in;

    const int n0 = blockIdx.x * 128;
    const int m0 = blockIdx.y * 128;

    float acc[4][4][4];
    #pragma unroll
    for (int i = 0; i < 4; i++)
        #pragma unroll
        for (int j = 0; j < 4; j++)
            #pragma unroll
            for (int q = 0; q < 4; q++) acc[i][j][q] = 0.f;

    const int lrow = tid >> 3;
    const int lcol = (tid & 7) * 4;
    const float* aSrc = A  + (size_t)(m0 + lrow) * C + lcol;
    const float* bSrc = Bt + (size_t)(n0 + lrow) * C + lcol;

    auto issue = [&](int s) {
        const int k0 = s * 32;
        const uint32_t ab = smb + (uint32_t)((s % GSTAGES) * STAGEF) * 4;
        const uint32_t bb = ab + TILEF * 4;
        #pragma unroll
        for (int p = 0; p < 4; p++) {
            const uint32_t off = (uint32_t)((p * 32 + lrow) * LDSR + lcol) * 4;
            cp16(ab + off, aSrc + (size_t)(p * 32) * C + k0);
            cp16(bb + off, bSrc + (size_t)(p * 32) * C + k0);
        }
    };

    uint32_t aoff[4], boff[2];
    #pragma unroll
    for (int mf = 0; mf < 4; mf++) {
        const int row = wm * 64 + mf * 16 + (lg & 1) * 8 + lr8;
        aoff[mf] = (uint32_t)(row * LDSR + (lg >> 1) * 4) * 4;
    }
    #pragma unroll
    for (int p = 0; p < 2; p++) {
        const int row = wn * 32 + p * 16 + (lg >> 1) * 8 + lr8;
        boff[p] = (uint32_t)(row * LDSR + (lg & 1) * 4) * 4;
    }

    issue(0); CP_COMMIT();
    issue(1); CP_COMMIT();

    for (int s = 0; s < 16; s++) {
        CP_WAIT1();
        __syncthreads();
        if (s + 2 < 16) issue(s + 2);
        CP_COMMIT();

        const uint32_t ab = smb + (uint32_t)((s % GSTAGES) * STAGEF) * 4;
        const uint32_t bb = ab + TILEF * 4;
        #pragma unroll
        for (int ks = 0; ks < 4; ks++) {
            const uint32_t kb = ks * 32;
            uint32_t af[4][4], bf[2][4];
            #pragma unroll
            for (int mf = 0; mf < 4; mf++)
                LDM4(af[mf][0], af[mf][1], af[mf][2], af[mf][3], ab + aoff[mf] + kb);
            #pragma unroll
            for (int p = 0; p < 2; p++)
                LDM4(bf[p][0], bf[p][1], bf[p][2], bf[p][3], bb + boff[p] + kb);
            #pragma unroll
            for (int mf = 0; mf < 4; mf++)
                #pragma unroll
                for (int p = 0; p < 2; p++) {
                    mma_tf32(acc[mf][2 * p],     af[mf], &bf[p][0]);
                    mma_tf32(acc[mf][2 * p + 1], af[mf], &bf[p][2]);
                }
        }
    }

    #pragma unroll
    for (int nf = 0; nf < 4; nf++) {
        const int j = n0 + wn * 32 + nf * 8 + 2 * tig;
        const float b0 = bias[j], b1 = bias[j + 1];
        #pragma unroll
        for (int mf = 0; mf < 4; mf++) {
            const int mrow0 = m0 + wm * 64 + mf * 16 + gid;
            #pragma unroll
            for (int half = 0; half < 2; half++) {
                const int m = mrow0 + half * 8;
                float vx = acc[mf][nf][half * 2 + 0] + b0;
                float vy = acc[mf][nf][half * 2 + 1] + b1;
                if (mode == 0) {
                    vx = rndtf(vx); vy = rndtf(vy);
                    const int kind = j >> 9;
                    const int hh = (j >> 6) & 7;
                    const int dd = j & 63;
                    const int bb2 = m >> 8;
                    const int tt = m & 255;
                    if (kind == 2) {   // V transposed: [b,h,d,t]
                        float* dst = g_v + (((size_t)(bb2 * H + hh)) * D + dd) * T + tt;
                        dst[0] = vx;
                        dst[T] = vy;
                    } else {
                        float* bufp = (kind == 0) ? g_q : g_k;
                        float* dst = bufp + (((size_t)(bb2 * H + hh)) * T + tt) * D + dd;
                        *(float2*)dst = make_float2(vx, vy);
                    }
                } else {
                    float* dst = outp + (size_t)m * C + j;
                    *(float2*)dst = make_float2(vx, vy);
                }
            }
        }
    }
}

// ---------------------------------------------------------------------------
// Online-softmax tensor-core attention, S chunked by 128, K/V share a buffer.
// One block per (qtile 64 q-rows, h, b), 8 warps (wm 2 x wn 4). 2 CTA/SM.
// Per chunk: load K -> QK^T (mma) -> mask+max (regs+smem exchange) ->
//            rescale O/l, exp, store P, partial sums -> load V into K buffer ->
//            PV (mma) accumulate into O regs.
// ---------------------------------------------------------------------------
constexpr int QSTR = 68;    // Q / K-chunk row stride (floats)
constexpr int CSTR = 132;   // St / Vt row stride (floats)
constexpr int AQ_OFF  = 0;                      // Qs[64][68]          4352
constexpr int AKV_OFF = AQ_OFF + 64 * QSTR;     // KV: Ks[128][68] or Vt[64][132]  8704
constexpr int AS_OFF  = AKV_OFF + 8704;         // St[64][132]         8448
constexpr int APM_OFF = AS_OFF + 64 * CSTR;     // pmax[4][64]
constexpr int APS_OFF = APM_OFF + 256;          // psum[4][64]
constexpr int ATTN_FLOATS = APS_OFF + 256;      // 22016 floats
constexpr size_t SMEM_ATTN = (size_t)ATTN_FLOATS * 4;   // 88,064 B -> 2 CTA/SM

__global__ void __launch_bounds__(256, 2) attn_kernel()
{
    extern __shared__ float smf[];
    const uint32_t smb = smem_u32(smf);
    float* Qs = smf + AQ_OFF;
    float* KV = smf + AKV_OFF;
    float* St = smf + AS_OFF;
    float* pmx = smf + APM_OFF;
    float* psm = smf + APS_OFF;

    const int qt  = blockIdx.x;            // 0..3
    const int hh  = blockIdx.y;
    const int bb  = blockIdx.z;
    const int tid = threadIdx.x;
    const int wid = tid >> 5;
    const int lid = tid & 31;
    const int gid = lid >> 2, tig = lid & 3;
    const int lg = lid >> 3, lr8 = lid & 7;
    const int wm = wid & 1;                // 32 q-rows each
    const int wn = wid >> 1;               // 4 col/d groups
    const int t0 = qt * 64;
    const int S_lim = t0 + 64;
    const int nchunks = (S_lim + 127) >> 7;

    const float* qp = g_q + ((size_t)(bb * H + hh)) * T * D;
    const float* kp = g_k + ((size_t)(bb * H + hh)) * T * D;
    const float* vp = g_v + ((size_t)(bb * H + hh)) * D * T;   // [d][t]

    // load Q once
    for (int idx = tid; idx < 64 * 16; idx += 256) {
        int i = idx >> 4, dg = (idx & 15) * 4;
        *(float4*)&Qs[i * QSTR + dg] = *(const float4*)(qp + (size_t)(t0 + i) * D + dg);
    }

    // per-thread running state
    float O[2][2][4];
    float m_run[2][2], l_run[2][2];
    #pragma unroll
    for (int i = 0; i < 2; i++)
        #pragma unroll
        for (int j = 0; j < 2; j++) {
            m_run[i][j] = -1e30f; l_run[i][j] = 0.f;
            #pragma unroll
            for (int q = 0; q < 4; q++) O[i][j][q] = 0.f;
        }

    uint32_t qoff[2];
    #pragma unroll
    for (int mf = 0; mf < 2; mf++) {
        const int row = wm * 32 + mf * 16 + (lg & 1) * 8 + lr8;
        qoff[mf] = smb + (uint32_t)(AQ_OFF + row * QSTR + (lg >> 1) * 4) * 4;
    }
    const float C1L = 0.18033688011112042f;    // 0.125 * log2(e)

    for (int c = 0; c < nchunks; c++) {
        const int s0 = c << 7;
        const int sc = min(128, S_lim - s0);       // 64 or 128
        const int NWc = sc >> 2;                   // 16 or 32
        const int nfmax = NWc >> 3;                // 2 or 4
        const int npair = nfmax >> 1;              // 1 or 2
        const int t_hi = t0 + wm * 32 + 31;

        // ---- load K chunk ----
        for (int idx = tid; idx < sc * 16; idx += 256) {
            int s = idx >> 4, dg = (idx & 15) * 4;
            *(float4*)&KV[s * QSTR + dg] = *(const float4*)(kp + (size_t)(s0 + s) * D + dg);
        }
        __syncthreads();    // (a) K (and Q on first iter) ready

        // ---- QK^T ----
        float acc[2][4][4];
        #pragma unroll
        for (int i = 0; i < 2; i++)
            #pragma unroll
            for (int j = 0; j < 4; j++)
                #pragma unroll
                for (int q = 0; q < 4; q++) acc[i][j][q] = 0.f;

        #pragma unroll
        for (int ks = 0; ks < 8; ks++) {
            const uint32_t kb = ks * 32;
            uint32_t af[2][4];
            #pragma unroll
            for (int mf = 0; mf < 2; mf++)
                LDM4(af[mf][0], af[mf][1], af[mf][2], af[mf][3], qoff[mf] + kb);
            #pragma unroll
            for (int p = 0; p < 2; p++) {
                if (p >= npair) break;
                const int n_lo = wn * NWc + p * 16;
                const int n_abs = s0 + n_lo;
                if (n_abs > t_hi) continue;
                const int rowk = n_lo + (lg >> 1) * 8 + lr8;
                uint32_t bf[4];
                LDM4(bf[0], bf[1], bf[2], bf[3],
                     smb + (uint32_t)(AKV_OFF + rowk * QSTR + (lg & 1) * 4) * 4 + kb);
                #pragma unroll
                for (int mf = 0; mf < 2; mf++) {
                    mma_tf32(acc[mf][2 * p],     af[mf], &bf[0]);
                    if (n_abs + 8 <= t_hi)
                        mma_tf32(acc[mf][2 * p + 1], af[mf], &bf[2]);
                }
            }
        }

        // ---- mask + per-warp max ----
        #pragma unroll
        for (int mf = 0; mf < 2; mf++) {
            const int r0 = wm * 32 + mf * 16 + gid;
            const int tg0 = t0 + r0, tg1 = tg0 + 8;
            float w0 = -1e30f, w1 = -1e30f;
            #pragma unroll
            for (int nf = 0; nf < 4; nf++) {
                if (nf >= nfmax) break;
                const int sA = s0 + wn * NWc + nf * 8 + 2 * tig;
                float* a = acc[mf][nf];
                a[0] = (sA     <= tg0) ? a[0] : -1e30f;
                a[1] = (sA + 1 <= tg0) ? a[1] : -1e30f;
                a[2] = (sA     <= tg1) ? a[2] : -1e30f;
                a[3] = (sA + 1 <= tg1) ? a[3] : -1e30f;
                w0 = fmaxf(w0, fmaxf(a[0], a[1]));
                w1 = fmaxf(w1, fmaxf(a[2], a[3]));
            }
            w0 = fmaxf(w0, __shfl_xor_sync(0xffffffffu, w0, 1));
            w0 = fmaxf(w0, __shfl_xor_sync(0xffffffffu, w0, 2));
            w1 = fmaxf(w1, __shfl_xor_sync(0xffffffffu, w1, 1));
            w1 = fmaxf(w1, __shfl_xor_sync(0xffffffffu, w1, 2));
            if (tig == 0) {
                pmx[wn * 64 + r0]     = w0;
                pmx[wn * 64 + r0 + 8] = w1;
            }
        }
        __syncthreads();    // (b) pmx ready

        // ---- rescale + exp + store P + partial sums ----
        #pragma unroll
        for (int mf = 0; mf < 2; mf++) {
            const int r0 = wm * 32 + mf * 16 + gid;
            #pragma unroll
            for (int half = 0; half < 2; half++) {
                const int lrow = r0 + half * 8;
                float mc = fmaxf(fmaxf(pmx[lrow], pmx[64 + lrow]),
                                 fmaxf(pmx[128 + lrow], pmx[192 + lrow]));
                float mnew = fmaxf(m_run[mf][half], mc);
                float alpha = ex2f((m_run[mf][half] - mnew) * C1L);
                m_run[mf][half] = mnew;
                l_run[mf][half] *= alpha;
                #pragma unroll
                for (int nf = 0; nf < 2; nf++) {
                    O[mf][nf][half * 2 + 0] *= alpha;
                    O[mf][nf][half * 2 + 1] *= alpha;
                }
                float ps = 0.f;
                #pragma unroll
                for (int nf = 0; nf < 4; nf++) {
                    if (nf >= nfmax) break;
                    const int sl = wn * NWc + nf * 8 + 2 * tig;
                    float* a = acc[mf][nf];
                    float e0 = ex2f((a[half * 2 + 0] - mnew) * C1L);
                    float e1 = ex2f((a[half * 2 + 1] - mnew) * C1L);
                    ps += e0 + e1;
                    *(float2*)&St[lrow * CSTR + sl] = make_float2(e0, e1);
                }
                ps += __shfl_xor_sync(0xffffffffu, ps, 1);
                ps += __shfl_xor_sync(0xffffffffu, ps, 2);
                if (tig == 0) psm[wn * 64 + lrow] = ps;
            }
        }
        __syncthreads();    // (c) St/psm ready; K dead

        // ---- load V chunk into KV (overwrite K) + l update ----
        {
            const int sqsh = (sc == 128) ? 5 : 4;          // float4s per row = 32/16
            const int nq = 64 << sqsh >> 2;                // 64 * (sc/4) / ... total float4s
            for (int idx = tid; idx < 64 * (sc >> 2); idx += 256) {
                int d = idx >> sqsh, sg = (idx & ((1 << sqsh) - 1)) * 4;
                *(float4*)&KV[d * CSTR + sg] = *(const float4*)(vp + (size_t)d * T + s0 + sg);
            }
            (void)nq;
        }
        #pragma unroll
        for (int mf = 0; mf < 2; mf++) {
            const int r0 = wm * 32 + mf * 16 + gid;
            #pragma unroll
            for (int half = 0; half < 2; half++) {
                const int lrow = r0 + half * 8;
                l_run[mf][half] += psm[lrow] + psm[64 + lrow] +
                                   psm[128 + lrow] + psm[192 + lrow];
            }
        }
        __syncthreads();    // (d) V ready

        // ---- PV accumulate ----
        {
            uint32_t soff[2];
            #pragma unroll
            for (int mf = 0; mf < 2; mf++) {
                const int row = wm * 32 + mf * 16 + (lg & 1) * 8 + lr8;
                soff[mf] = smb + (uint32_t)(AS_OFF + row * CSTR + (lg >> 1) * 4) * 4;
            }
            const int rowv = wn * 16 + (lg >> 1) * 8 + lr8;
            const uint32_t voff = smb + (uint32_t)(AKV_OFF + rowv * CSTR + (lg & 1) * 4) * 4;

            const int kst = sc >> 3;
            for (int ks = 0; ks < kst; ks++) {
                const uint32_t kb = ks * 32;
                uint32_t af[2][4], bf[4];
                LDM4(bf[0], bf[1], bf[2], bf[3], voff + kb);
                #pragma unroll
                for (int mf = 0; mf < 2; mf++) {
                    LDM4(af[mf][0], af[mf][1], af[mf][2], af[mf][3], soff[mf] + kb);
                    mma_tf32(O[mf][0], af[mf], &bf[0]);
                    mma_tf32(O[mf][1], af[mf], &bf[2]);
                }
            }
        }
        __syncthreads();    // (e) KV/St free for next chunk
    }

    // ---- epilogue: /l, round, write g_attn ----
    #pragma unroll
    for (int mf = 0; mf < 2; mf++) {
        const int row0 = wm * 32 + mf * 16 + gid;
        #pragma unroll
        for (int half = 0; half < 2; half++) {
            const int i = row0 + half * 8;
            const float inv = 1.f / l_run[mf][half];
            #pragma unroll
            for (int nf = 0; nf < 2; nf++) {
                const int col = wn * 16 + nf * 8 + 2 * tig;
                float2 v;
                v.x = rndtf(O[mf][nf][half * 2 + 0] * inv);
                v.y = rndtf(O[mf][nf][half * 2 + 1] * inv);
                *(float2*)(g_attn + ((size_t)bb * T + t0 + i) * C + hh * D + col) = v;
            }
        }
    }
}

// ---------------------------------------------------------------------------
extern "C" void kernel_launch(void* const* d_in, const int* in_sizes, int n_in,
                              void* d_out, int out_size)
{
    const float* x  = (const float*)d_in[0];
    const float* wq = (const float*)d_in[1];
    const float* wk = (const float*)d_in[2];
    const float* wv = (const float*)d_in[3];
    const float* bq = (const float*)d_in[4];
    const float* bk = (const float*)d_in[5];
    const float* bv = (const float*)d_in[6];
    const float* wo = (const float*)d_in[7];
    const float* bo = (const float*)d_in[8];
    float* out = (float*)d_out;

    cudaFuncSetAttribute(attn_kernel, cudaFuncAttributeMaxDynamicSharedMemorySize,
                         (int)SMEM_ATTN);
    cudaFuncSetAttribute(gemm_mma_kernel, cudaFuncAttributeMaxDynamicSharedMemorySize,
                         SMEM_GEMM_BYTES);

    prep_kernel<<<PREP_BLOCKS, 256>>>((const float4*)x, wq, wk, wv, wo, bq, bk, bv);
    gemm_mma_kernel<<<dim3(N3 / 128, M / 128), 256, SMEM_GEMM_BYTES>>>(nullptr, nullptr, 0);
    attn_kernel<<<dim3(T / 64, H, B), 256, SMEM_ATTN>>>();
    gemm_mma_kernel<<<dim3(C / 128, M / 128), 256, SMEM_GEMM_BYTES>>>(bo, out, 1);
}